// round 1
// baseline (speedup 1.0000x reference)
#include <cuda_runtime.h>
#include <math.h>

#define D_MODEL 1024
#define NUM_HEADS 16
#define D_HEAD 64
#define BATCH 2
#define SEQ 2048
#define BHN (BATCH*NUM_HEADS)

// -------- scratch (static device memory; no runtime allocation) --------
__device__ float g_q[(size_t)BATCH*SEQ*D_MODEL];            // 16 MB
__device__ float g_k[(size_t)BATCH*SEQ*D_MODEL];            // 16 MB
__device__ float g_v[(size_t)BATCH*SEQ*D_MODEL];            // 16 MB
__device__ float g_qer[(size_t)BHN*SEQ*SEQ];                // 512 MB

// ============================================================
// Kernel 1: Q/K/V projection.  out[m,e] = sum_d x[m,d]*W[e,d] + b[e]
// Tile 128x128, kc=16, 256 threads, 8x8 micro-tile.
// ============================================================
__global__ __launch_bounds__(256)
void qkv_kernel(const float* __restrict__ x,
                const float* __restrict__ Wq, const float* __restrict__ bq,
                const float* __restrict__ Wk, const float* __restrict__ bk,
                const float* __restrict__ Wv, const float* __restrict__ bv)
{
    const float* W; const float* bias; float* outp;
    if (blockIdx.z == 0)      { W = Wq; bias = bq; outp = g_q; }
    else if (blockIdx.z == 1) { W = Wk; bias = bk; outp = g_k; }
    else                      { W = Wv; bias = bv; outp = g_v; }

    __shared__ float As[16][132];
    __shared__ float Bs[16][132];

    const int m0 = blockIdx.y * 128;
    const int n0 = blockIdx.x * 128;
    const int tid = threadIdx.x;
    const int ty = tid >> 4;   // 0..15 -> rows ty*8..
    const int tx = tid & 15;   // 0..15 -> cols tx*8..

    float acc[8][8];
#pragma unroll
    for (int i = 0; i < 8; i++)
#pragma unroll
        for (int j = 0; j < 8; j++) acc[i][j] = 0.f;

    for (int k0 = 0; k0 < D_MODEL; k0 += 16) {
#pragma unroll
        for (int i = 0; i < 2; i++) {
            int idx = tid + i * 256;        // 0..511
            int row = idx >> 2;             // 0..127
            int c4  = (idx & 3) * 4;        // 0,4,8,12
            float4 a = *(const float4*)(x + (size_t)(m0 + row) * D_MODEL + k0 + c4);
            As[c4 + 0][row] = a.x; As[c4 + 1][row] = a.y;
            As[c4 + 2][row] = a.z; As[c4 + 3][row] = a.w;
            float4 w = *(const float4*)(W + (size_t)(n0 + row) * D_MODEL + k0 + c4);
            Bs[c4 + 0][row] = w.x; Bs[c4 + 1][row] = w.y;
            Bs[c4 + 2][row] = w.z; Bs[c4 + 3][row] = w.w;
        }
        __syncthreads();
#pragma unroll
        for (int kk = 0; kk < 16; kk++) {
            float af[8], bf[8];
#pragma unroll
            for (int i = 0; i < 8; i++) af[i] = As[kk][ty * 8 + i];
#pragma unroll
            for (int j = 0; j < 8; j++) bf[j] = Bs[kk][tx * 8 + j];
#pragma unroll
            for (int i = 0; i < 8; i++)
#pragma unroll
                for (int j = 0; j < 8; j++) acc[i][j] += af[i] * bf[j];
        }
        __syncthreads();
    }

#pragma unroll
    for (int i = 0; i < 8; i++) {
        int row = m0 + ty * 8 + i;
#pragma unroll
        for (int j = 0; j < 8; j += 4) {
            int col = n0 + tx * 8 + j;
            float4 r;
            r.x = acc[i][j + 0] + bias[col + 0];
            r.y = acc[i][j + 1] + bias[col + 1];
            r.z = acc[i][j + 2] + bias[col + 2];
            r.w = acc[i][j + 3] + bias[col + 3];
            *(float4*)(outp + (size_t)row * D_MODEL + col) = r;
        }
    }
}

// ============================================================
// Kernel 2: QEr[bh][s][j] = q_head[s,:] . Er[j,:]
// Only tiles intersecting the causal band (s+j >= SEQ-1) are computed.
// Tile 128x128, K = 64, kc = 16.
// ============================================================
__global__ __launch_bounds__(256)
void qer_kernel(const float* __restrict__ Er)
{
    const int bh = blockIdx.z;
    const int b = bh >> 4, h = bh & 15;
    const int j0 = blockIdx.x * 128;
    const int s0 = blockIdx.y * 128;
    if (s0 + j0 + 254 < SEQ - 1) return;   // no (s,j) in tile with s+j >= SEQ-1

    __shared__ float As[16][132];
    __shared__ float Bs[16][132];

    const int tid = threadIdx.x;
    const int ty = tid >> 4;
    const int tx = tid & 15;

    const float* qb = g_q + ((size_t)b * SEQ) * D_MODEL + (size_t)h * D_HEAD;

    float acc[8][8];
#pragma unroll
    for (int i = 0; i < 8; i++)
#pragma unroll
        for (int j = 0; j < 8; j++) acc[i][j] = 0.f;

    for (int k0 = 0; k0 < D_HEAD; k0 += 16) {
#pragma unroll
        for (int i = 0; i < 2; i++) {
            int idx = tid + i * 256;
            int row = idx >> 2;
            int c4  = (idx & 3) * 4;
            float4 a = *(const float4*)(qb + (size_t)(s0 + row) * D_MODEL + k0 + c4);
            As[c4 + 0][row] = a.x; As[c4 + 1][row] = a.y;
            As[c4 + 2][row] = a.z; As[c4 + 3][row] = a.w;
            float4 e = *(const float4*)(Er + (size_t)(j0 + row) * D_HEAD + k0 + c4);
            Bs[c4 + 0][row] = e.x; Bs[c4 + 1][row] = e.y;
            Bs[c4 + 2][row] = e.z; Bs[c4 + 3][row] = e.w;
        }
        __syncthreads();
#pragma unroll
        for (int kk = 0; kk < 16; kk++) {
            float af[8], bf[8];
#pragma unroll
            for (int i = 0; i < 8; i++) af[i] = As[kk][ty * 8 + i];
#pragma unroll
            for (int j = 0; j < 8; j++) bf[j] = Bs[kk][tx * 8 + j];
#pragma unroll
            for (int i = 0; i < 8; i++)
#pragma unroll
                for (int j = 0; j < 8; j++) acc[i][j] += af[i] * bf[j];
        }
        __syncthreads();
    }

    float* dst = g_qer + (size_t)bh * SEQ * SEQ;
#pragma unroll
    for (int i = 0; i < 8; i++) {
        size_t rowoff = (size_t)(s0 + ty * 8 + i) * SEQ;
#pragma unroll
        for (int j = 0; j < 8; j += 4) {
            int col = j0 + tx * 8 + j;
            float4 r = make_float4(acc[i][j], acc[i][j + 1], acc[i][j + 2], acc[i][j + 3]);
            *(float4*)(dst + rowoff + col) = r;
        }
    }
}

// ============================================================
// Kernel 3: fused causal flash attention with relative bias.
// Bq=128 query rows / block, Bk=64 keys / tile, 256 threads.
// Thread (ty,tx): rows ty*8..ty*8+7, score cols / out dims tx*4..tx*4+3.
// ============================================================
#define BQ 128
#define BK 64
#define QSP 132
#define KSP 68
#define VSP 68
#define PSP 65
#define ATT_SMEM_FLOATS (64*QSP + 64*KSP + BK*VSP + BQ*PSP)
#define ATT_SMEM_BYTES (ATT_SMEM_FLOATS * 4)

__global__ __launch_bounds__(256, 2)
void attn_kernel(float* __restrict__ out)
{
    const int qt = blockIdx.x;
    const int bh = blockIdx.y;
    const int b = bh >> 4, h = bh & 15;
    const int s0 = qt * BQ;

    extern __shared__ float smem[];
    float* qsT = smem;                    // [64][QSP]  qsT[d*QSP + r]
    float* ksT = qsT + 64 * QSP;          // [64][KSP]  ksT[d*KSP + t]
    float* vs  = ksT + 64 * KSP;          // [BK][VSP]  vs[t*VSP + d]
    float* ps  = vs  + BK * VSP;          // [BQ][PSP]  rel tile, then P

    const int tid = threadIdx.x;
    const int ty = tid >> 4;
    const int tx = tid & 15;

    const float* qb  = g_q + ((size_t)b * SEQ) * D_MODEL + (size_t)h * D_HEAD;
    const float* kb  = g_k + ((size_t)b * SEQ) * D_MODEL + (size_t)h * D_HEAD;
    const float* vb  = g_v + ((size_t)b * SEQ) * D_MODEL + (size_t)h * D_HEAD;
    const float* qer = g_qer + (size_t)bh * SEQ * SEQ;

    // load Q tile transposed
#pragma unroll
    for (int i = 0; i < 8; i++) {
        int idx = tid + i * 256;
        int row = idx >> 4;              // 0..127
        int c4  = (idx & 15) * 4;        // 0..60
        float4 qv = *(const float4*)(qb + (size_t)(s0 + row) * D_MODEL + c4);
        qsT[(c4 + 0) * QSP + row] = qv.x;
        qsT[(c4 + 1) * QSP + row] = qv.y;
        qsT[(c4 + 2) * QSP + row] = qv.z;
        qsT[(c4 + 3) * QSP + row] = qv.w;
    }

    float m[8], l[8], o[8][4];
#pragma unroll
    for (int i = 0; i < 8; i++) {
        m[i] = -1e30f; l[i] = 0.f;
        o[i][0] = o[i][1] = o[i][2] = o[i][3] = 0.f;
    }

    const int ktmax = 2 * qt + 1;
    for (int kt = 0; kt <= ktmax; kt++) {
        const int t0 = kt * BK;
        __syncthreads();   // previous tile fully consumed

        // load K (transposed) and V tiles
#pragma unroll
        for (int i = 0; i < 4; i++) {
            int idx = tid + i * 256;
            int row = idx >> 4;          // 0..63
            int c4  = (idx & 15) * 4;
            float4 kv = *(const float4*)(kb + (size_t)(t0 + row) * D_MODEL + c4);
            ksT[(c4 + 0) * KSP + row] = kv.x;
            ksT[(c4 + 1) * KSP + row] = kv.y;
            ksT[(c4 + 2) * KSP + row] = kv.z;
            ksT[(c4 + 3) * KSP + row] = kv.w;
            float4 vv = *(const float4*)(vb + (size_t)(t0 + row) * D_MODEL + c4);
            *(float4*)(vs + row * VSP + c4) = vv;
        }

        // load skewed relative-bias tile: rel[r][t] = QEr[s0+r][SEQ-1 + t0+t - (s0+r)]
        // (clamped index for masked t>s entries; value is discarded by the mask)
#pragma unroll
        for (int i = 0; i < 32; i++) {
            int idx = tid + i * 256;
            int r = idx >> 6;            // 0..127
            int t = idx & 63;
            int j = (SEQ - 1) + t0 + t - s0 - r;
            j = j > (SEQ - 1) ? (SEQ - 1) : j;
            ps[r * PSP + t] = qer[(size_t)(s0 + r) * SEQ + j];
        }
        __syncthreads();

        // scores = Q.K^T (register tiled)
        float sc[8][4];
#pragma unroll
        for (int i = 0; i < 8; i++)
#pragma unroll
            for (int j = 0; j < 4; j++) sc[i][j] = 0.f;

#pragma unroll 8
        for (int d = 0; d < 64; d++) {
            float4 bf = *(const float4*)(ksT + d * KSP + tx * 4);
            float af[8];
#pragma unroll
            for (int i = 0; i < 8; i++) af[i] = qsT[d * QSP + ty * 8 + i];
#pragma unroll
            for (int i = 0; i < 8; i++) {
                sc[i][0] += af[i] * bf.x;
                sc[i][1] += af[i] * bf.y;
                sc[i][2] += af[i] * bf.z;
                sc[i][3] += af[i] * bf.w;
            }
        }

        // add rel bias, scale, causal mask, online softmax
#pragma unroll
        for (int i = 0; i < 8; i++) {
            const int r  = ty * 8 + i;
            const int sg = s0 + r;
            float rowm = -1e30f;
#pragma unroll
            for (int j = 0; j < 4; j++) {
                int tg = t0 + tx * 4 + j;
                float v = (sc[i][j] + ps[r * PSP + tx * 4 + j]) * 0.125f;
                v = (tg <= sg) ? v : -1e30f;
                sc[i][j] = v;
                rowm = fmaxf(rowm, v);
            }
#pragma unroll
            for (int off = 8; off > 0; off >>= 1)
                rowm = fmaxf(rowm, __shfl_xor_sync(0xffffffffu, rowm, off, 16));
            float mnew  = fmaxf(m[i], rowm);
            float alpha = __expf(m[i] - mnew);
            m[i] = mnew;
            float lsum = 0.f;
#pragma unroll
            for (int j = 0; j < 4; j++) {
                float pv = __expf(sc[i][j] - mnew);
                sc[i][j] = pv;
                lsum += pv;
            }
            l[i] = l[i] * alpha + lsum;
            o[i][0] *= alpha; o[i][1] *= alpha; o[i][2] *= alpha; o[i][3] *= alpha;
            // write P over the rel tile (each element owned by exactly this thread)
#pragma unroll
            for (int j = 0; j < 4; j++) ps[r * PSP + tx * 4 + j] = sc[i][j];
        }
        __syncthreads();

        // O += P.V
#pragma unroll 4
        for (int t = 0; t < 64; t++) {
            float4 vf = *(const float4*)(vs + t * VSP + tx * 4);
#pragma unroll
            for (int i = 0; i < 8; i++) {
                float pv = ps[(ty * 8 + i) * PSP + t];
                o[i][0] += pv * vf.x;
                o[i][1] += pv * vf.y;
                o[i][2] += pv * vf.z;
                o[i][3] += pv * vf.w;
            }
        }
    }

    // finalize: reduce l across the 16 col-threads, normalize, store
    float* outb = out + ((size_t)b * SEQ) * D_MODEL + (size_t)h * D_HEAD;
#pragma unroll
    for (int i = 0; i < 8; i++) {
        float lv = l[i];
#pragma unroll
        for (int off = 8; off > 0; off >>= 1)
            lv += __shfl_xor_sync(0xffffffffu, lv, off, 16);
        float inv = 1.f / lv;
        float4 ov = make_float4(o[i][0] * inv, o[i][1] * inv, o[i][2] * inv, o[i][3] * inv);
        *(float4*)(outb + (size_t)(s0 + ty * 8 + i) * D_MODEL + tx * 4) = ov;
    }
}

// ============================================================
// launcher
// ============================================================
extern "C" void kernel_launch(void* const* d_in, const int* in_sizes, int n_in,
                              void* d_out, int out_size)
{
    const float* x  = (const float*)d_in[0];
    const float* Wq = (const float*)d_in[1];
    const float* bq = (const float*)d_in[2];
    const float* Wk = (const float*)d_in[3];
    const float* bk = (const float*)d_in[4];
    const float* Wv = (const float*)d_in[5];
    const float* bv = (const float*)d_in[6];
    const float* Er = (const float*)d_in[7];
    float* out = (float*)d_out;

    cudaFuncSetAttribute(attn_kernel, cudaFuncAttributeMaxDynamicSharedMemorySize,
                         ATT_SMEM_BYTES);

    dim3 g1(D_MODEL / 128, (BATCH * SEQ) / 128, 3);
    qkv_kernel<<<g1, 256>>>(x, Wq, bq, Wk, bk, Wv, bv);

    dim3 g2(SEQ / 128, SEQ / 128, BHN);
    qer_kernel<<<g2, 256>>>(Er);

    dim3 g3(SEQ / BQ, BHN);
    attn_kernel<<<g3, 256, ATT_SMEM_BYTES>>>(out);
}

// round 2
// speedup vs baseline: 1.0328x; 1.0328x over previous
#include <cuda_runtime.h>
#include <math.h>

#define D_MODEL 1024
#define NUM_HEADS 16
#define D_HEAD 64
#define BATCH 2
#define SEQ 2048
#define BHN (BATCH*NUM_HEADS)

// -------- scratch (static device memory; no runtime allocation) --------
__device__ float g_q[(size_t)BATCH*SEQ*D_MODEL];            // 16 MB
__device__ float g_k[(size_t)BATCH*SEQ*D_MODEL];            // 16 MB
__device__ float g_v[(size_t)BATCH*SEQ*D_MODEL];            // 16 MB
__device__ float g_qer[(size_t)BHN*SEQ*SEQ];                // 512 MB

// ============================================================
// Kernel 1: Q/K/V projection.  out[m,e] = sum_d x[m,d]*W[e,d] + b[e]
// Tile 128x128, kc=16, 256 threads, 8x8 micro-tile.
// Double-buffered smem, register-staged global prefetch.
// ============================================================
__global__ __launch_bounds__(256, 2)
void qkv_kernel(const float* __restrict__ x,
                const float* __restrict__ Wq, const float* __restrict__ bq,
                const float* __restrict__ Wk, const float* __restrict__ bk,
                const float* __restrict__ Wv, const float* __restrict__ bv)
{
    const float* W; const float* bias; float* outp;
    if (blockIdx.z == 0)      { W = Wq; bias = bq; outp = g_q; }
    else if (blockIdx.z == 1) { W = Wk; bias = bk; outp = g_k; }
    else                      { W = Wv; bias = bv; outp = g_v; }

    __shared__ float As[2][16][132];
    __shared__ float Bs[2][16][132];

    const int m0 = blockIdx.y * 128;
    const int n0 = blockIdx.x * 128;
    const int tid = threadIdx.x;
    const int ty = tid >> 4;
    const int tx = tid & 15;

    // loader geometry (each thread loads 2 float4 of A and 2 of B per chunk)
    const int lrow0 = tid >> 2;                 // 0..63
    const int lrow1 = lrow0 + 64;               // 64..127
    const int lc4   = (tid & 3) * 4;            // 0,4,8,12

    const float* xr0 = x + (size_t)(m0 + lrow0) * D_MODEL + lc4;
    const float* xr1 = x + (size_t)(m0 + lrow1) * D_MODEL + lc4;
    const float* wr0 = W + (size_t)(n0 + lrow0) * D_MODEL + lc4;
    const float* wr1 = W + (size_t)(n0 + lrow1) * D_MODEL + lc4;

    float4 ra0, ra1, rw0, rw1;

    // prefetch chunk 0
    ra0 = *(const float4*)(xr0);
    ra1 = *(const float4*)(xr1);
    rw0 = *(const float4*)(wr0);
    rw1 = *(const float4*)(wr1);

    // store to buffer 0
    As[0][lc4+0][lrow0]=ra0.x; As[0][lc4+1][lrow0]=ra0.y; As[0][lc4+2][lrow0]=ra0.z; As[0][lc4+3][lrow0]=ra0.w;
    As[0][lc4+0][lrow1]=ra1.x; As[0][lc4+1][lrow1]=ra1.y; As[0][lc4+2][lrow1]=ra1.z; As[0][lc4+3][lrow1]=ra1.w;
    Bs[0][lc4+0][lrow0]=rw0.x; Bs[0][lc4+1][lrow0]=rw0.y; Bs[0][lc4+2][lrow0]=rw0.z; Bs[0][lc4+3][lrow0]=rw0.w;
    Bs[0][lc4+0][lrow1]=rw1.x; Bs[0][lc4+1][lrow1]=rw1.y; Bs[0][lc4+2][lrow1]=rw1.z; Bs[0][lc4+3][lrow1]=rw1.w;
    __syncthreads();

    float acc[8][8];
#pragma unroll
    for (int i = 0; i < 8; i++)
#pragma unroll
        for (int j = 0; j < 8; j++) acc[i][j] = 0.f;

    for (int k0 = 0; k0 < D_MODEL; k0 += 16) {
        const int buf = (k0 >> 4) & 1;
        const bool has_next = (k0 + 16) < D_MODEL;
        if (has_next) {
            ra0 = *(const float4*)(xr0 + k0 + 16);
            ra1 = *(const float4*)(xr1 + k0 + 16);
            rw0 = *(const float4*)(wr0 + k0 + 16);
            rw1 = *(const float4*)(wr1 + k0 + 16);
        }
#pragma unroll
        for (int kk = 0; kk < 16; kk++) {
            float4 a0 = *(const float4*)(&As[buf][kk][ty * 8]);
            float4 a1 = *(const float4*)(&As[buf][kk][ty * 8 + 4]);
            float4 b0 = *(const float4*)(&Bs[buf][kk][tx * 8]);
            float4 b1 = *(const float4*)(&Bs[buf][kk][tx * 8 + 4]);
            float af[8] = {a0.x,a0.y,a0.z,a0.w,a1.x,a1.y,a1.z,a1.w};
            float bf[8] = {b0.x,b0.y,b0.z,b0.w,b1.x,b1.y,b1.z,b1.w};
#pragma unroll
            for (int i = 0; i < 8; i++)
#pragma unroll
                for (int j = 0; j < 8; j++) acc[i][j] += af[i] * bf[j];
        }
        if (has_next) {
            const int nb = buf ^ 1;
            As[nb][lc4+0][lrow0]=ra0.x; As[nb][lc4+1][lrow0]=ra0.y; As[nb][lc4+2][lrow0]=ra0.z; As[nb][lc4+3][lrow0]=ra0.w;
            As[nb][lc4+0][lrow1]=ra1.x; As[nb][lc4+1][lrow1]=ra1.y; As[nb][lc4+2][lrow1]=ra1.z; As[nb][lc4+3][lrow1]=ra1.w;
            Bs[nb][lc4+0][lrow0]=rw0.x; Bs[nb][lc4+1][lrow0]=rw0.y; Bs[nb][lc4+2][lrow0]=rw0.z; Bs[nb][lc4+3][lrow0]=rw0.w;
            Bs[nb][lc4+0][lrow1]=rw1.x; Bs[nb][lc4+1][lrow1]=rw1.y; Bs[nb][lc4+2][lrow1]=rw1.z; Bs[nb][lc4+3][lrow1]=rw1.w;
            __syncthreads();
        }
    }

#pragma unroll
    for (int i = 0; i < 8; i++) {
        int row = m0 + ty * 8 + i;
#pragma unroll
        for (int j = 0; j < 8; j += 4) {
            int col = n0 + tx * 8 + j;
            float4 r;
            r.x = acc[i][j + 0] + bias[col + 0];
            r.y = acc[i][j + 1] + bias[col + 1];
            r.z = acc[i][j + 2] + bias[col + 2];
            r.w = acc[i][j + 3] + bias[col + 3];
            *(float4*)(outp + (size_t)row * D_MODEL + col) = r;
        }
    }
}

// ============================================================
// Kernel 2: QEr[bh][s][j] = q_head[s,:] . Er[j,:]
// Tiles entirely outside causal band skipped. K = 64 in 4 chunks,
// double-buffered.
// ============================================================
__global__ __launch_bounds__(256, 2)
void qer_kernel(const float* __restrict__ Er)
{
    const int bh = blockIdx.z;
    const int b = bh >> 4, h = bh & 15;
    const int j0 = blockIdx.x * 128;
    const int s0 = blockIdx.y * 128;
    if (s0 + j0 + 254 < SEQ - 1) return;

    __shared__ float As[2][16][132];
    __shared__ float Bs[2][16][132];

    const int tid = threadIdx.x;
    const int ty = tid >> 4;
    const int tx = tid & 15;

    const int lrow0 = tid >> 2;
    const int lrow1 = lrow0 + 64;
    const int lc4   = (tid & 3) * 4;

    const float* qb = g_q + ((size_t)b * SEQ) * D_MODEL + (size_t)h * D_HEAD;
    const float* qr0 = qb + (size_t)(s0 + lrow0) * D_MODEL + lc4;
    const float* qr1 = qb + (size_t)(s0 + lrow1) * D_MODEL + lc4;
    const float* er0 = Er + (size_t)(j0 + lrow0) * D_HEAD + lc4;
    const float* er1 = Er + (size_t)(j0 + lrow1) * D_HEAD + lc4;

    float4 ra0, ra1, rw0, rw1;
    ra0 = *(const float4*)(qr0);
    ra1 = *(const float4*)(qr1);
    rw0 = *(const float4*)(er0);
    rw1 = *(const float4*)(er1);

    As[0][lc4+0][lrow0]=ra0.x; As[0][lc4+1][lrow0]=ra0.y; As[0][lc4+2][lrow0]=ra0.z; As[0][lc4+3][lrow0]=ra0.w;
    As[0][lc4+0][lrow1]=ra1.x; As[0][lc4+1][lrow1]=ra1.y; As[0][lc4+2][lrow1]=ra1.z; As[0][lc4+3][lrow1]=ra1.w;
    Bs[0][lc4+0][lrow0]=rw0.x; Bs[0][lc4+1][lrow0]=rw0.y; Bs[0][lc4+2][lrow0]=rw0.z; Bs[0][lc4+3][lrow0]=rw0.w;
    Bs[0][lc4+0][lrow1]=rw1.x; Bs[0][lc4+1][lrow1]=rw1.y; Bs[0][lc4+2][lrow1]=rw1.z; Bs[0][lc4+3][lrow1]=rw1.w;
    __syncthreads();

    float acc[8][8];
#pragma unroll
    for (int i = 0; i < 8; i++)
#pragma unroll
        for (int j = 0; j < 8; j++) acc[i][j] = 0.f;

    for (int k0 = 0; k0 < D_HEAD; k0 += 16) {
        const int buf = (k0 >> 4) & 1;
        const bool has_next = (k0 + 16) < D_HEAD;
        if (has_next) {
            ra0 = *(const float4*)(qr0 + k0 + 16);
            ra1 = *(const float4*)(qr1 + k0 + 16);
            rw0 = *(const float4*)(er0 + k0 + 16);
            rw1 = *(const float4*)(er1 + k0 + 16);
        }
#pragma unroll
        for (int kk = 0; kk < 16; kk++) {
            float4 a0 = *(const float4*)(&As[buf][kk][ty * 8]);
            float4 a1 = *(const float4*)(&As[buf][kk][ty * 8 + 4]);
            float4 b0 = *(const float4*)(&Bs[buf][kk][tx * 8]);
            float4 b1 = *(const float4*)(&Bs[buf][kk][tx * 8 + 4]);
            float af[8] = {a0.x,a0.y,a0.z,a0.w,a1.x,a1.y,a1.z,a1.w};
            float bf[8] = {b0.x,b0.y,b0.z,b0.w,b1.x,b1.y,b1.z,b1.w};
#pragma unroll
            for (int i = 0; i < 8; i++)
#pragma unroll
                for (int j = 0; j < 8; j++) acc[i][j] += af[i] * bf[j];
        }
        if (has_next) {
            const int nb = buf ^ 1;
            As[nb][lc4+0][lrow0]=ra0.x; As[nb][lc4+1][lrow0]=ra0.y; As[nb][lc4+2][lrow0]=ra0.z; As[nb][lc4+3][lrow0]=ra0.w;
            As[nb][lc4+0][lrow1]=ra1.x; As[nb][lc4+1][lrow1]=ra1.y; As[nb][lc4+2][lrow1]=ra1.z; As[nb][lc4+3][lrow1]=ra1.w;
            Bs[nb][lc4+0][lrow0]=rw0.x; Bs[nb][lc4+1][lrow0]=rw0.y; Bs[nb][lc4+2][lrow0]=rw0.z; Bs[nb][lc4+3][lrow0]=rw0.w;
            Bs[nb][lc4+0][lrow1]=rw1.x; Bs[nb][lc4+1][lrow1]=rw1.y; Bs[nb][lc4+2][lrow1]=rw1.z; Bs[nb][lc4+3][lrow1]=rw1.w;
            __syncthreads();
        }
    }

    float* dst = g_qer + (size_t)bh * SEQ * SEQ;
#pragma unroll
    for (int i = 0; i < 8; i++) {
        size_t rowoff = (size_t)(s0 + ty * 8 + i) * SEQ;
#pragma unroll
        for (int j = 0; j < 8; j += 4) {
            int col = j0 + tx * 8 + j;
            float4 r = make_float4(acc[i][j], acc[i][j + 1], acc[i][j + 2], acc[i][j + 3]);
            *(float4*)(dst + rowoff + col) = r;
        }
    }
}

// ============================================================
// Kernel 3: fused causal flash attention with relative bias.
// Bq=128 query rows / block, Bk=64 keys / tile, 256 threads.
// All shared accesses aligned to float4 (PSP=68).
// ============================================================
#define BQ 128
#define BK 64
#define QSP 132
#define KSP 68
#define VSP 68
#define PSP 68
#define ATT_SMEM_FLOATS (64*QSP + 64*KSP + BK*VSP + BQ*PSP)
#define ATT_SMEM_BYTES (ATT_SMEM_FLOATS * 4)

__global__ __launch_bounds__(256, 2)
void attn_kernel(float* __restrict__ out)
{
    const int qt = blockIdx.x;
    const int bh = blockIdx.y;
    const int b = bh >> 4, h = bh & 15;
    const int s0 = qt * BQ;

    extern __shared__ float smem[];
    float* qsT = smem;                    // [64][QSP]
    float* ksT = qsT + 64 * QSP;          // [64][KSP]
    float* vs  = ksT + 64 * KSP;          // [BK][VSP]
    float* ps  = vs  + BK * VSP;          // [BQ][PSP]  rel tile, then P

    const int tid = threadIdx.x;
    const int ty = tid >> 4;
    const int tx = tid & 15;

    const float* qb  = g_q + ((size_t)b * SEQ) * D_MODEL + (size_t)h * D_HEAD;
    const float* kb  = g_k + ((size_t)b * SEQ) * D_MODEL + (size_t)h * D_HEAD;
    const float* vb  = g_v + ((size_t)b * SEQ) * D_MODEL + (size_t)h * D_HEAD;
    const float* qer = g_qer + (size_t)bh * SEQ * SEQ;

    // load Q tile transposed
#pragma unroll
    for (int i = 0; i < 8; i++) {
        int idx = tid + i * 256;
        int row = idx >> 4;
        int c4  = (idx & 15) * 4;
        float4 qv = *(const float4*)(qb + (size_t)(s0 + row) * D_MODEL + c4);
        qsT[(c4 + 0) * QSP + row] = qv.x;
        qsT[(c4 + 1) * QSP + row] = qv.y;
        qsT[(c4 + 2) * QSP + row] = qv.z;
        qsT[(c4 + 3) * QSP + row] = qv.w;
    }

    float m[8], l[8], o[8][4];
#pragma unroll
    for (int i = 0; i < 8; i++) {
        m[i] = -1e30f; l[i] = 0.f;
        o[i][0] = o[i][1] = o[i][2] = o[i][3] = 0.f;
    }

    const int ktmax = 2 * qt + 1;
    for (int kt = 0; kt <= ktmax; kt++) {
        const int t0 = kt * BK;
        __syncthreads();

        // load K (transposed) and V tiles
#pragma unroll
        for (int i = 0; i < 4; i++) {
            int idx = tid + i * 256;
            int row = idx >> 4;
            int c4  = (idx & 15) * 4;
            float4 kv = *(const float4*)(kb + (size_t)(t0 + row) * D_MODEL + c4);
            ksT[(c4 + 0) * KSP + row] = kv.x;
            ksT[(c4 + 1) * KSP + row] = kv.y;
            ksT[(c4 + 2) * KSP + row] = kv.z;
            ksT[(c4 + 3) * KSP + row] = kv.w;
            float4 vv = *(const float4*)(vb + (size_t)(t0 + row) * D_MODEL + c4);
            *(float4*)(vs + row * VSP + c4) = vv;
        }

        // load skewed relative-bias tile: rel[r][t] = QEr[s0+r][SEQ-1 + t0+t - (s0+r)]
#pragma unroll
        for (int i = 0; i < 32; i++) {
            int idx = tid + i * 256;
            int r = idx >> 6;
            int t = idx & 63;
            int j = (SEQ - 1) + t0 + t - s0 - r;
            j = j > (SEQ - 1) ? (SEQ - 1) : j;
            ps[r * PSP + t] = qer[(size_t)(s0 + r) * SEQ + j];
        }
        __syncthreads();

        // scores = Q.K^T
        float sc[8][4];
#pragma unroll
        for (int i = 0; i < 8; i++)
#pragma unroll
            for (int j = 0; j < 4; j++) sc[i][j] = 0.f;

#pragma unroll 8
        for (int d = 0; d < 64; d++) {
            float4 bf = *(const float4*)(ksT + d * KSP + tx * 4);
            float4 a0 = *(const float4*)(qsT + d * QSP + ty * 8);
            float4 a1 = *(const float4*)(qsT + d * QSP + ty * 8 + 4);
            float af[8] = {a0.x,a0.y,a0.z,a0.w,a1.x,a1.y,a1.z,a1.w};
#pragma unroll
            for (int i = 0; i < 8; i++) {
                sc[i][0] += af[i] * bf.x;
                sc[i][1] += af[i] * bf.y;
                sc[i][2] += af[i] * bf.z;
                sc[i][3] += af[i] * bf.w;
            }
        }

        // add rel bias, scale, causal mask, online softmax
#pragma unroll
        for (int i = 0; i < 8; i++) {
            const int r  = ty * 8 + i;
            const int sg = s0 + r;
            float4 rel = *(const float4*)(ps + r * PSP + tx * 4);
            float relv[4] = {rel.x, rel.y, rel.z, rel.w};
            float rowm = -1e30f;
#pragma unroll
            for (int j = 0; j < 4; j++) {
                int tg = t0 + tx * 4 + j;
                float v = (sc[i][j] + relv[j]) * 0.125f;
                v = (tg <= sg) ? v : -1e30f;
                sc[i][j] = v;
                rowm = fmaxf(rowm, v);
            }
#pragma unroll
            for (int off = 8; off > 0; off >>= 1)
                rowm = fmaxf(rowm, __shfl_xor_sync(0xffffffffu, rowm, off, 16));
            float mnew  = fmaxf(m[i], rowm);
            float alpha = __expf(m[i] - mnew);
            m[i] = mnew;
            float lsum = 0.f;
#pragma unroll
            for (int j = 0; j < 4; j++) {
                float pv = __expf(sc[i][j] - mnew);
                sc[i][j] = pv;
                lsum += pv;
            }
            l[i] = l[i] * alpha + lsum;
            o[i][0] *= alpha; o[i][1] *= alpha; o[i][2] *= alpha; o[i][3] *= alpha;
            float4 pst = make_float4(sc[i][0], sc[i][1], sc[i][2], sc[i][3]);
            *(float4*)(ps + r * PSP + tx * 4) = pst;
        }
        __syncthreads();

        // O += P.V  (LDS.128 for both P rows and V rows)
#pragma unroll 4
        for (int t4 = 0; t4 < 16; t4++) {
            float4 vf0 = *(const float4*)(vs + (t4*4 + 0) * VSP + tx * 4);
            float4 vf1 = *(const float4*)(vs + (t4*4 + 1) * VSP + tx * 4);
            float4 vf2 = *(const float4*)(vs + (t4*4 + 2) * VSP + tx * 4);
            float4 vf3 = *(const float4*)(vs + (t4*4 + 3) * VSP + tx * 4);
#pragma unroll
            for (int i = 0; i < 8; i++) {
                float4 p4 = *(const float4*)(ps + (ty * 8 + i) * PSP + t4 * 4);
                o[i][0] += p4.x * vf0.x + p4.y * vf1.x + p4.z * vf2.x + p4.w * vf3.x;
                o[i][1] += p4.x * vf0.y + p4.y * vf1.y + p4.z * vf2.y + p4.w * vf3.y;
                o[i][2] += p4.x * vf0.z + p4.y * vf1.z + p4.z * vf2.z + p4.w * vf3.z;
                o[i][3] += p4.x * vf0.w + p4.y * vf1.w + p4.z * vf2.w + p4.w * vf3.w;
            }
        }
    }

    // finalize
    float* outb = out + ((size_t)b * SEQ) * D_MODEL + (size_t)h * D_HEAD;
#pragma unroll
    for (int i = 0; i < 8; i++) {
        float lv = l[i];
#pragma unroll
        for (int off = 8; off > 0; off >>= 1)
            lv += __shfl_xor_sync(0xffffffffu, lv, off, 16);
        float inv = 1.f / lv;
        float4 ov = make_float4(o[i][0] * inv, o[i][1] * inv, o[i][2] * inv, o[i][3] * inv);
        *(float4*)(outb + (size_t)(s0 + ty * 8 + i) * D_MODEL + tx * 4) = ov;
    }
}

// ============================================================
// launcher
// ============================================================
extern "C" void kernel_launch(void* const* d_in, const int* in_sizes, int n_in,
                              void* d_out, int out_size)
{
    const float* x  = (const float*)d_in[0];
    const float* Wq = (const float*)d_in[1];
    const float* bq = (const float*)d_in[2];
    const float* Wk = (const float*)d_in[3];
    const float* bk = (const float*)d_in[4];
    const float* Wv = (const float*)d_in[5];
    const float* bv = (const float*)d_in[6];
    const float* Er = (const float*)d_in[7];
    float* out = (float*)d_out;

    cudaFuncSetAttribute(attn_kernel, cudaFuncAttributeMaxDynamicSharedMemorySize,
                         ATT_SMEM_BYTES);

    dim3 g1(D_MODEL / 128, (BATCH * SEQ) / 128, 3);
    qkv_kernel<<<g1, 256>>>(x, Wq, bq, Wk, bk, Wv, bv);

    dim3 g2(SEQ / 128, SEQ / 128, BHN);
    qer_kernel<<<g2, 256>>>(Er);

    dim3 g3(SEQ / BQ, BHN);
    attn_kernel<<<g3, 256, ATT_SMEM_BYTES>>>(out);
}

// round 3
// speedup vs baseline: 1.6205x; 1.5691x over previous
#include <cuda_runtime.h>
#include <math.h>
#include <stdint.h>

#define D_MODEL 1024
#define NUM_HEADS 16
#define D_HEAD 64
#define BATCH 2
#define SEQ 2048
#define BHN (BATCH*NUM_HEADS)

// -------- scratch (static device memory; no runtime allocation) --------
__device__ float g_q[(size_t)BATCH*SEQ*D_MODEL];            // 16 MB
__device__ float g_k[(size_t)BATCH*SEQ*D_MODEL];            // 16 MB
__device__ float g_v[(size_t)BATCH*SEQ*D_MODEL];            // 16 MB
__device__ float g_qer[(size_t)BHN*SEQ*SEQ];                // 512 MB

// ---------------- tf32 mma helpers ----------------
__device__ __forceinline__ uint32_t f2tf(float x) {
    uint32_t r;
    asm("cvt.rna.tf32.f32 %0, %1;" : "=r"(r) : "f"(x));
    return r;
}
__device__ __forceinline__ float f2tf_f(float x) {
    return __uint_as_float(f2tf(x));
}
__device__ __forceinline__ void mma_tf32(float& c0, float& c1, float& c2, float& c3,
                                         uint32_t a0, uint32_t a1, uint32_t a2, uint32_t a3,
                                         uint32_t b0, uint32_t b1) {
    asm volatile(
        "mma.sync.aligned.m16n8k8.row.col.f32.tf32.tf32.f32 "
        "{%0,%1,%2,%3}, {%4,%5,%6,%7}, {%8,%9}, {%0,%1,%2,%3};"
        : "+f"(c0), "+f"(c1), "+f"(c2), "+f"(c3)
        : "r"(a0), "r"(a1), "r"(a2), "r"(a3), "r"(b0), "r"(b1));
}

// smem geometry for tensor-core GEMMs: [2 buf][128 rows][36] floats each for A and B
#define GP 36
#define GEMM_SMEM_FLOATS (2*128*GP*2)
#define GEMM_SMEM_BYTES (GEMM_SMEM_FLOATS*4)

// ============================================================
// Kernel 1 (tensor core): Q/K/V projection.
// out[m,e] = sum_d x[m,d]*W[e,d] + b[e]; 128x128 tile, KC=32.
// 8 warps: warp_m = wid>>2 (0..1), warp_n = wid&3 (0..3); warp tile 64x32.
// ============================================================
__global__ __launch_bounds__(256, 2)
void qkv_tc_kernel(const float* __restrict__ x,
                   const float* __restrict__ Wq, const float* __restrict__ bq,
                   const float* __restrict__ Wk, const float* __restrict__ bk,
                   const float* __restrict__ Wv, const float* __restrict__ bv)
{
    const float* W; const float* bias; float* outp;
    if (blockIdx.z == 0)      { W = Wq; bias = bq; outp = g_q; }
    else if (blockIdx.z == 1) { W = Wk; bias = bk; outp = g_k; }
    else                      { W = Wv; bias = bv; outp = g_v; }

    extern __shared__ float sm[];
    float* As = sm;                 // [2][128][GP]
    float* Bs = sm + 2*128*GP;      // [2][128][GP]

    const int m0 = blockIdx.y * 128;
    const int n0 = blockIdx.x * 128;
    const int tid = threadIdx.x;
    const int wid = tid >> 5;
    const int lane = tid & 31;
    const int gid = lane >> 2;      // 0..7
    const int tig = lane & 3;       // 0..3
    const int wm = wid >> 2;        // 0..1
    const int wn = wid & 3;         // 0..3

    const float* Ag = x + (size_t)m0 * D_MODEL;
    const float* Bg = W + (size_t)n0 * D_MODEL;

    float c[4][4][4];
#pragma unroll
    for (int mt = 0; mt < 4; mt++)
#pragma unroll
        for (int nt = 0; nt < 4; nt++)
#pragma unroll
            for (int r = 0; r < 4; r++) c[mt][nt][r] = 0.f;

    const int lrow = tid >> 3;            // base row for loads (with +i*32)
    const int lc4  = (tid & 7) * 4;       // 0..28

    float4 pa[4], pb[4];
    // prefetch chunk 0
#pragma unroll
    for (int i = 0; i < 4; i++) {
        pa[i] = *(const float4*)(Ag + (size_t)(lrow + i*32) * D_MODEL + lc4);
        pb[i] = *(const float4*)(Bg + (size_t)(lrow + i*32) * D_MODEL + lc4);
    }
#pragma unroll
    for (int i = 0; i < 4; i++) {
        float* da = As + (lrow + i*32) * GP + lc4;
        da[0]=f2tf_f(pa[i].x); da[1]=f2tf_f(pa[i].y); da[2]=f2tf_f(pa[i].z); da[3]=f2tf_f(pa[i].w);
        float* db = Bs + (lrow + i*32) * GP + lc4;
        db[0]=f2tf_f(pb[i].x); db[1]=f2tf_f(pb[i].y); db[2]=f2tf_f(pb[i].z); db[3]=f2tf_f(pb[i].w);
    }
    __syncthreads();

    for (int k0 = 0; k0 < D_MODEL; k0 += 32) {
        const int buf = (k0 >> 5) & 1;
        const bool has_next = (k0 + 32) < D_MODEL;
        if (has_next) {
#pragma unroll
            for (int i = 0; i < 4; i++) {
                pa[i] = *(const float4*)(Ag + (size_t)(lrow + i*32) * D_MODEL + k0 + 32 + lc4);
                pb[i] = *(const float4*)(Bg + (size_t)(lrow + i*32) * D_MODEL + k0 + 32 + lc4);
            }
        }
        const float* Ab = As + buf * 128 * GP;
        const float* Bb = Bs + buf * 128 * GP;
#pragma unroll
        for (int ks = 0; ks < 4; ks++) {
            const int kk = ks * 8;
            uint32_t a[4][4];
#pragma unroll
            for (int mt = 0; mt < 4; mt++) {
                const float* p = Ab + (wm*64 + mt*16 + gid) * GP + kk + tig;
                a[mt][0] = __float_as_uint(p[0]);
                a[mt][2] = __float_as_uint(p[4]);
                a[mt][1] = __float_as_uint(p[8*GP]);
                a[mt][3] = __float_as_uint(p[8*GP + 4]);
            }
#pragma unroll
            for (int nt = 0; nt < 4; nt++) {
                const float* q = Bb + (wn*32 + nt*8 + gid) * GP + kk + tig;
                uint32_t b0 = __float_as_uint(q[0]);
                uint32_t b1 = __float_as_uint(q[4]);
#pragma unroll
                for (int mt = 0; mt < 4; mt++)
                    mma_tf32(c[mt][nt][0], c[mt][nt][1], c[mt][nt][2], c[mt][nt][3],
                             a[mt][0], a[mt][1], a[mt][2], a[mt][3], b0, b1);
            }
        }
        if (has_next) {
            const int nb = buf ^ 1;
#pragma unroll
            for (int i = 0; i < 4; i++) {
                float* da = As + nb*128*GP + (lrow + i*32) * GP + lc4;
                da[0]=f2tf_f(pa[i].x); da[1]=f2tf_f(pa[i].y); da[2]=f2tf_f(pa[i].z); da[3]=f2tf_f(pa[i].w);
                float* db = Bs + nb*128*GP + (lrow + i*32) * GP + lc4;
                db[0]=f2tf_f(pb[i].x); db[1]=f2tf_f(pb[i].y); db[2]=f2tf_f(pb[i].z); db[3]=f2tf_f(pb[i].w);
            }
            __syncthreads();
        }
    }

    // epilogue: add bias, store
#pragma unroll
    for (int nt = 0; nt < 4; nt++) {
        const int col = n0 + wn*32 + nt*8 + 2*tig;
        const float2 bb = *(const float2*)(bias + col);
#pragma unroll
        for (int mt = 0; mt < 4; mt++) {
            const int row = m0 + wm*64 + mt*16 + gid;
            float2 r0 = make_float2(c[mt][nt][0] + bb.x, c[mt][nt][1] + bb.y);
            float2 r1 = make_float2(c[mt][nt][2] + bb.x, c[mt][nt][3] + bb.y);
            *(float2*)(outp + (size_t)row * D_MODEL + col) = r0;
            *(float2*)(outp + (size_t)(row + 8) * D_MODEL + col) = r1;
        }
    }
}

// ============================================================
// Kernel 2 (tensor core): QEr[bh][s][j] = q_head[s,:] . Er[j,:]
// K = 64 (2 chunks), band-skip.
// ============================================================
__global__ __launch_bounds__(256, 2)
void qer_tc_kernel(const float* __restrict__ Er)
{
    const int bh = blockIdx.z;
    const int b = bh >> 4, h = bh & 15;
    const int j0 = blockIdx.x * 128;
    const int s0 = blockIdx.y * 128;
    if (s0 + j0 + 254 < SEQ - 1) return;

    extern __shared__ float sm[];
    float* As = sm;
    float* Bs = sm + 2*128*GP;

    const int tid = threadIdx.x;
    const int wid = tid >> 5;
    const int lane = tid & 31;
    const int gid = lane >> 2;
    const int tig = lane & 3;
    const int wm = wid >> 2;
    const int wn = wid & 3;

    const float* Ag = g_q + ((size_t)b * SEQ + s0) * D_MODEL + (size_t)h * D_HEAD;
    const float* Bg = Er + (size_t)j0 * D_HEAD;

    float c[4][4][4];
#pragma unroll
    for (int mt = 0; mt < 4; mt++)
#pragma unroll
        for (int nt = 0; nt < 4; nt++)
#pragma unroll
            for (int r = 0; r < 4; r++) c[mt][nt][r] = 0.f;

    const int lrow = tid >> 3;
    const int lc4  = (tid & 7) * 4;

    float4 pa[4], pb[4];
#pragma unroll
    for (int i = 0; i < 4; i++) {
        pa[i] = *(const float4*)(Ag + (size_t)(lrow + i*32) * D_MODEL + lc4);
        pb[i] = *(const float4*)(Bg + (size_t)(lrow + i*32) * D_HEAD + lc4);
    }
#pragma unroll
    for (int i = 0; i < 4; i++) {
        float* da = As + (lrow + i*32) * GP + lc4;
        da[0]=f2tf_f(pa[i].x); da[1]=f2tf_f(pa[i].y); da[2]=f2tf_f(pa[i].z); da[3]=f2tf_f(pa[i].w);
        float* db = Bs + (lrow + i*32) * GP + lc4;
        db[0]=f2tf_f(pb[i].x); db[1]=f2tf_f(pb[i].y); db[2]=f2tf_f(pb[i].z); db[3]=f2tf_f(pb[i].w);
    }
    __syncthreads();

    for (int k0 = 0; k0 < D_HEAD; k0 += 32) {
        const int buf = (k0 >> 5) & 1;
        const bool has_next = (k0 + 32) < D_HEAD;
        if (has_next) {
#pragma unroll
            for (int i = 0; i < 4; i++) {
                pa[i] = *(const float4*)(Ag + (size_t)(lrow + i*32) * D_MODEL + k0 + 32 + lc4);
                pb[i] = *(const float4*)(Bg + (size_t)(lrow + i*32) * D_HEAD + k0 + 32 + lc4);
            }
        }
        const float* Ab = As + buf * 128 * GP;
        const float* Bb = Bs + buf * 128 * GP;
#pragma unroll
        for (int ks = 0; ks < 4; ks++) {
            const int kk = ks * 8;
            uint32_t a[4][4];
#pragma unroll
            for (int mt = 0; mt < 4; mt++) {
                const float* p = Ab + (wm*64 + mt*16 + gid) * GP + kk + tig;
                a[mt][0] = __float_as_uint(p[0]);
                a[mt][2] = __float_as_uint(p[4]);
                a[mt][1] = __float_as_uint(p[8*GP]);
                a[mt][3] = __float_as_uint(p[8*GP + 4]);
            }
#pragma unroll
            for (int nt = 0; nt < 4; nt++) {
                const float* q = Bb + (wn*32 + nt*8 + gid) * GP + kk + tig;
                uint32_t b0 = __float_as_uint(q[0]);
                uint32_t b1 = __float_as_uint(q[4]);
#pragma unroll
                for (int mt = 0; mt < 4; mt++)
                    mma_tf32(c[mt][nt][0], c[mt][nt][1], c[mt][nt][2], c[mt][nt][3],
                             a[mt][0], a[mt][1], a[mt][2], a[mt][3], b0, b1);
            }
        }
        if (has_next) {
            const int nb = buf ^ 1;
#pragma unroll
            for (int i = 0; i < 4; i++) {
                float* da = As + nb*128*GP + (lrow + i*32) * GP + lc4;
                da[0]=f2tf_f(pa[i].x); da[1]=f2tf_f(pa[i].y); da[2]=f2tf_f(pa[i].z); da[3]=f2tf_f(pa[i].w);
                float* db = Bs + nb*128*GP + (lrow + i*32) * GP + lc4;
                db[0]=f2tf_f(pb[i].x); db[1]=f2tf_f(pb[i].y); db[2]=f2tf_f(pb[i].z); db[3]=f2tf_f(pb[i].w);
            }
            __syncthreads();
        }
    }

    float* dst = g_qer + (size_t)bh * SEQ * SEQ;
#pragma unroll
    for (int nt = 0; nt < 4; nt++) {
        const int col = j0 + wn*32 + nt*8 + 2*tig;
#pragma unroll
        for (int mt = 0; mt < 4; mt++) {
            const int row = s0 + wm*64 + mt*16 + gid;
            *(float2*)(dst + (size_t)row * SEQ + col) = make_float2(c[mt][nt][0], c[mt][nt][1]);
            *(float2*)(dst + (size_t)(row + 8) * SEQ + col) = make_float2(c[mt][nt][2], c[mt][nt][3]);
        }
    }
}

// ============================================================
// Kernel 3: fused causal flash attention with relative bias (fp32 SIMT).
// ============================================================
#define BQ 128
#define BK 64
#define QSP 132
#define KSP 68
#define VSP 68
#define PSP 68
#define ATT_SMEM_FLOATS (64*QSP + 64*KSP + BK*VSP + BQ*PSP)
#define ATT_SMEM_BYTES (ATT_SMEM_FLOATS * 4)

__global__ __launch_bounds__(256, 2)
void attn_kernel(float* __restrict__ out)
{
    const int qt = blockIdx.x;
    const int bh = blockIdx.y;
    const int b = bh >> 4, h = bh & 15;
    const int s0 = qt * BQ;

    extern __shared__ float smem[];
    float* qsT = smem;
    float* ksT = qsT + 64 * QSP;
    float* vs  = ksT + 64 * KSP;
    float* ps  = vs  + BK * VSP;

    const int tid = threadIdx.x;
    const int ty = tid >> 4;
    const int tx = tid & 15;

    const float* qb  = g_q + ((size_t)b * SEQ) * D_MODEL + (size_t)h * D_HEAD;
    const float* kb  = g_k + ((size_t)b * SEQ) * D_MODEL + (size_t)h * D_HEAD;
    const float* vb  = g_v + ((size_t)b * SEQ) * D_MODEL + (size_t)h * D_HEAD;
    const float* qer = g_qer + (size_t)bh * SEQ * SEQ;

#pragma unroll
    for (int i = 0; i < 8; i++) {
        int idx = tid + i * 256;
        int row = idx >> 4;
        int c4  = (idx & 15) * 4;
        float4 qv = *(const float4*)(qb + (size_t)(s0 + row) * D_MODEL + c4);
        qsT[(c4 + 0) * QSP + row] = qv.x;
        qsT[(c4 + 1) * QSP + row] = qv.y;
        qsT[(c4 + 2) * QSP + row] = qv.z;
        qsT[(c4 + 3) * QSP + row] = qv.w;
    }

    float m[8], l[8], o[8][4];
#pragma unroll
    for (int i = 0; i < 8; i++) {
        m[i] = -1e30f; l[i] = 0.f;
        o[i][0] = o[i][1] = o[i][2] = o[i][3] = 0.f;
    }

    const int ktmax = 2 * qt + 1;
    for (int kt = 0; kt <= ktmax; kt++) {
        const int t0 = kt * BK;
        __syncthreads();

#pragma unroll
        for (int i = 0; i < 4; i++) {
            int idx = tid + i * 256;
            int row = idx >> 4;
            int c4  = (idx & 15) * 4;
            float4 kv = *(const float4*)(kb + (size_t)(t0 + row) * D_MODEL + c4);
            ksT[(c4 + 0) * KSP + row] = kv.x;
            ksT[(c4 + 1) * KSP + row] = kv.y;
            ksT[(c4 + 2) * KSP + row] = kv.z;
            ksT[(c4 + 3) * KSP + row] = kv.w;
            float4 vv = *(const float4*)(vb + (size_t)(t0 + row) * D_MODEL + c4);
            *(float4*)(vs + row * VSP + c4) = vv;
        }

#pragma unroll
        for (int i = 0; i < 32; i++) {
            int idx = tid + i * 256;
            int r = idx >> 6;
            int t = idx & 63;
            int j = (SEQ - 1) + t0 + t - s0 - r;
            j = j > (SEQ - 1) ? (SEQ - 1) : j;
            ps[r * PSP + t] = qer[(size_t)(s0 + r) * SEQ + j];
        }
        __syncthreads();

        float sc[8][4];
#pragma unroll
        for (int i = 0; i < 8; i++)
#pragma unroll
            for (int j = 0; j < 4; j++) sc[i][j] = 0.f;

#pragma unroll 8
        for (int d = 0; d < 64; d++) {
            float4 bf = *(const float4*)(ksT + d * KSP + tx * 4);
            float4 a0 = *(const float4*)(qsT + d * QSP + ty * 8);
            float4 a1 = *(const float4*)(qsT + d * QSP + ty * 8 + 4);
            float af[8] = {a0.x,a0.y,a0.z,a0.w,a1.x,a1.y,a1.z,a1.w};
#pragma unroll
            for (int i = 0; i < 8; i++) {
                sc[i][0] += af[i] * bf.x;
                sc[i][1] += af[i] * bf.y;
                sc[i][2] += af[i] * bf.z;
                sc[i][3] += af[i] * bf.w;
            }
        }

#pragma unroll
        for (int i = 0; i < 8; i++) {
            const int r  = ty * 8 + i;
            const int sg = s0 + r;
            float4 rel = *(const float4*)(ps + r * PSP + tx * 4);
            float relv[4] = {rel.x, rel.y, rel.z, rel.w};
            float rowm = -1e30f;
#pragma unroll
            for (int j = 0; j < 4; j++) {
                int tg = t0 + tx * 4 + j;
                float v = (sc[i][j] + relv[j]) * 0.125f;
                v = (tg <= sg) ? v : -1e30f;
                sc[i][j] = v;
                rowm = fmaxf(rowm, v);
            }
#pragma unroll
            for (int off = 8; off > 0; off >>= 1)
                rowm = fmaxf(rowm, __shfl_xor_sync(0xffffffffu, rowm, off, 16));
            float mnew  = fmaxf(m[i], rowm);
            float alpha = __expf(m[i] - mnew);
            m[i] = mnew;
            float lsum = 0.f;
#pragma unroll
            for (int j = 0; j < 4; j++) {
                float pv = __expf(sc[i][j] - mnew);
                sc[i][j] = pv;
                lsum += pv;
            }
            l[i] = l[i] * alpha + lsum;
            o[i][0] *= alpha; o[i][1] *= alpha; o[i][2] *= alpha; o[i][3] *= alpha;
            float4 pst = make_float4(sc[i][0], sc[i][1], sc[i][2], sc[i][3]);
            *(float4*)(ps + r * PSP + tx * 4) = pst;
        }
        __syncthreads();

#pragma unroll 4
        for (int t4 = 0; t4 < 16; t4++) {
            float4 vf0 = *(const float4*)(vs + (t4*4 + 0) * VSP + tx * 4);
            float4 vf1 = *(const float4*)(vs + (t4*4 + 1) * VSP + tx * 4);
            float4 vf2 = *(const float4*)(vs + (t4*4 + 2) * VSP + tx * 4);
            float4 vf3 = *(const float4*)(vs + (t4*4 + 3) * VSP + tx * 4);
#pragma unroll
            for (int i = 0; i < 8; i++) {
                float4 p4 = *(const float4*)(ps + (ty * 8 + i) * PSP + t4 * 4);
                o[i][0] += p4.x * vf0.x + p4.y * vf1.x + p4.z * vf2.x + p4.w * vf3.x;
                o[i][1] += p4.x * vf0.y + p4.y * vf1.y + p4.z * vf2.y + p4.w * vf3.y;
                o[i][2] += p4.x * vf0.z + p4.y * vf1.z + p4.z * vf2.z + p4.w * vf3.z;
                o[i][3] += p4.x * vf0.w + p4.y * vf1.w + p4.z * vf2.w + p4.w * vf3.w;
            }
        }
    }

    float* outb = out + ((size_t)b * SEQ) * D_MODEL + (size_t)h * D_HEAD;
#pragma unroll
    for (int i = 0; i < 8; i++) {
        float lv = l[i];
#pragma unroll
        for (int off = 8; off > 0; off >>= 1)
            lv += __shfl_xor_sync(0xffffffffu, lv, off, 16);
        float inv = 1.f / lv;
        float4 ov = make_float4(o[i][0] * inv, o[i][1] * inv, o[i][2] * inv, o[i][3] * inv);
        *(float4*)(outb + (size_t)(s0 + ty * 8 + i) * D_MODEL + tx * 4) = ov;
    }
}

// ============================================================
// launcher
// ============================================================
extern "C" void kernel_launch(void* const* d_in, const int* in_sizes, int n_in,
                              void* d_out, int out_size)
{
    const float* x  = (const float*)d_in[0];
    const float* Wq = (const float*)d_in[1];
    const float* bq = (const float*)d_in[2];
    const float* Wk = (const float*)d_in[3];
    const float* bk = (const float*)d_in[4];
    const float* Wv = (const float*)d_in[5];
    const float* bv = (const float*)d_in[6];
    const float* Er = (const float*)d_in[7];
    float* out = (float*)d_out;

    cudaFuncSetAttribute(qkv_tc_kernel, cudaFuncAttributeMaxDynamicSharedMemorySize,
                         GEMM_SMEM_BYTES);
    cudaFuncSetAttribute(qer_tc_kernel, cudaFuncAttributeMaxDynamicSharedMemorySize,
                         GEMM_SMEM_BYTES);
    cudaFuncSetAttribute(attn_kernel, cudaFuncAttributeMaxDynamicSharedMemorySize,
                         ATT_SMEM_BYTES);

    dim3 g1(D_MODEL / 128, (BATCH * SEQ) / 128, 3);
    qkv_tc_kernel<<<g1, 256, GEMM_SMEM_BYTES>>>(x, Wq, bq, Wk, bk, Wv, bv);

    dim3 g2(SEQ / 128, SEQ / 128, BHN);
    qer_tc_kernel<<<g2, 256, GEMM_SMEM_BYTES>>>(Er);

    dim3 g3(SEQ / BQ, BHN);
    attn_kernel<<<g3, 256, ATT_SMEM_BYTES>>>(out);
}

// round 4
// speedup vs baseline: 2.4799x; 1.5303x over previous
#include <cuda_runtime.h>
#include <math.h>
#include <stdint.h>

#define D_MODEL 1024
#define NUM_HEADS 16
#define D_HEAD 64
#define BATCH 2
#define SEQ 2048
#define BHN (BATCH*NUM_HEADS)

// -------- scratch (static device memory; no runtime allocation) --------
__device__ float g_q[(size_t)BATCH*SEQ*D_MODEL];            // 16 MB
__device__ float g_k[(size_t)BATCH*SEQ*D_MODEL];            // 16 MB
__device__ float g_vT[(size_t)BHN*D_HEAD*SEQ];              // 16 MB, [bh][d][s]
__device__ float g_qer[(size_t)BHN*SEQ*SEQ];                // 512 MB

// ---------------- tf32 mma helpers ----------------
__device__ __forceinline__ uint32_t f2tf(float x) {
    uint32_t r;
    asm("cvt.rna.tf32.f32 %0, %1;" : "=r"(r) : "f"(x));
    return r;
}
__device__ __forceinline__ float f2tf_f(float x) {
    return __uint_as_float(f2tf(x));
}
__device__ __forceinline__ void mma_tf32(float& c0, float& c1, float& c2, float& c3,
                                         uint32_t a0, uint32_t a1, uint32_t a2, uint32_t a3,
                                         uint32_t b0, uint32_t b1) {
    asm volatile(
        "mma.sync.aligned.m16n8k8.row.col.f32.tf32.tf32.f32 "
        "{%0,%1,%2,%3}, {%4,%5,%6,%7}, {%8,%9}, {%0,%1,%2,%3};"
        : "+f"(c0), "+f"(c1), "+f"(c2), "+f"(c3)
        : "r"(a0), "r"(a1), "r"(a2), "r"(a3), "r"(b0), "r"(b1));
}

// smem geometry for tensor-core GEMMs: [2 buf][128 rows][36] floats each for A and B
#define GP 36
#define GEMM_SMEM_FLOATS (2*128*GP*2)
#define GEMM_SMEM_BYTES (GEMM_SMEM_FLOATS*4)

// ============================================================
// Kernel 1 (tensor core): Q/K/V projection.
// out[m,e] = sum_d x[m,d]*W[e,d] + b[e]; 128x128 tile, KC=32.
// z==2 (V) writes transposed into g_vT[bh][d][s].
// ============================================================
__global__ __launch_bounds__(256, 2)
void qkv_tc_kernel(const float* __restrict__ x,
                   const float* __restrict__ Wq, const float* __restrict__ bq,
                   const float* __restrict__ Wk, const float* __restrict__ bk,
                   const float* __restrict__ Wv, const float* __restrict__ bv)
{
    const float* W; const float* bias; float* outp;
    if (blockIdx.z == 0)      { W = Wq; bias = bq; outp = g_q; }
    else if (blockIdx.z == 1) { W = Wk; bias = bk; outp = g_k; }
    else                      { W = Wv; bias = bv; outp = nullptr; }

    extern __shared__ float sm[];
    float* As = sm;                 // [2][128][GP]
    float* Bs = sm + 2*128*GP;      // [2][128][GP]

    const int m0 = blockIdx.y * 128;
    const int n0 = blockIdx.x * 128;
    const int tid = threadIdx.x;
    const int wid = tid >> 5;
    const int lane = tid & 31;
    const int gid = lane >> 2;
    const int tig = lane & 3;
    const int wm = wid >> 2;
    const int wn = wid & 3;

    const float* Ag = x + (size_t)m0 * D_MODEL;
    const float* Bg = W + (size_t)n0 * D_MODEL;

    float c[4][4][4];
#pragma unroll
    for (int mt = 0; mt < 4; mt++)
#pragma unroll
        for (int nt = 0; nt < 4; nt++)
#pragma unroll
            for (int r = 0; r < 4; r++) c[mt][nt][r] = 0.f;

    const int lrow = tid >> 3;
    const int lc4  = (tid & 7) * 4;

    float4 pa[4], pb[4];
#pragma unroll
    for (int i = 0; i < 4; i++) {
        pa[i] = *(const float4*)(Ag + (size_t)(lrow + i*32) * D_MODEL + lc4);
        pb[i] = *(const float4*)(Bg + (size_t)(lrow + i*32) * D_MODEL + lc4);
    }
#pragma unroll
    for (int i = 0; i < 4; i++) {
        float* da = As + (lrow + i*32) * GP + lc4;
        da[0]=f2tf_f(pa[i].x); da[1]=f2tf_f(pa[i].y); da[2]=f2tf_f(pa[i].z); da[3]=f2tf_f(pa[i].w);
        float* db = Bs + (lrow + i*32) * GP + lc4;
        db[0]=f2tf_f(pb[i].x); db[1]=f2tf_f(pb[i].y); db[2]=f2tf_f(pb[i].z); db[3]=f2tf_f(pb[i].w);
    }
    __syncthreads();

    for (int k0 = 0; k0 < D_MODEL; k0 += 32) {
        const int buf = (k0 >> 5) & 1;
        const bool has_next = (k0 + 32) < D_MODEL;
        if (has_next) {
#pragma unroll
            for (int i = 0; i < 4; i++) {
                pa[i] = *(const float4*)(Ag + (size_t)(lrow + i*32) * D_MODEL + k0 + 32 + lc4);
                pb[i] = *(const float4*)(Bg + (size_t)(lrow + i*32) * D_MODEL + k0 + 32 + lc4);
            }
        }
        const float* Ab = As + buf * 128 * GP;
        const float* Bb = Bs + buf * 128 * GP;
#pragma unroll
        for (int ks = 0; ks < 4; ks++) {
            const int kk = ks * 8;
            uint32_t a[4][4];
#pragma unroll
            for (int mt = 0; mt < 4; mt++) {
                const float* p = Ab + (wm*64 + mt*16 + gid) * GP + kk + tig;
                a[mt][0] = __float_as_uint(p[0]);
                a[mt][2] = __float_as_uint(p[4]);
                a[mt][1] = __float_as_uint(p[8*GP]);
                a[mt][3] = __float_as_uint(p[8*GP + 4]);
            }
#pragma unroll
            for (int nt = 0; nt < 4; nt++) {
                const float* q = Bb + (wn*32 + nt*8 + gid) * GP + kk + tig;
                uint32_t b0 = __float_as_uint(q[0]);
                uint32_t b1 = __float_as_uint(q[4]);
#pragma unroll
                for (int mt = 0; mt < 4; mt++)
                    mma_tf32(c[mt][nt][0], c[mt][nt][1], c[mt][nt][2], c[mt][nt][3],
                             a[mt][0], a[mt][1], a[mt][2], a[mt][3], b0, b1);
            }
        }
        if (has_next) {
            const int nb = buf ^ 1;
#pragma unroll
            for (int i = 0; i < 4; i++) {
                float* da = As + nb*128*GP + (lrow + i*32) * GP + lc4;
                da[0]=f2tf_f(pa[i].x); da[1]=f2tf_f(pa[i].y); da[2]=f2tf_f(pa[i].z); da[3]=f2tf_f(pa[i].w);
                float* db = Bs + nb*128*GP + (lrow + i*32) * GP + lc4;
                db[0]=f2tf_f(pb[i].x); db[1]=f2tf_f(pb[i].y); db[2]=f2tf_f(pb[i].z); db[3]=f2tf_f(pb[i].w);
            }
            __syncthreads();
        }
    }

    if (blockIdx.z != 2) {
        // row-major store with bias
#pragma unroll
        for (int nt = 0; nt < 4; nt++) {
            const int col = n0 + wn*32 + nt*8 + 2*tig;
            const float2 bb = *(const float2*)(bias + col);
#pragma unroll
            for (int mt = 0; mt < 4; mt++) {
                const int row = m0 + wm*64 + mt*16 + gid;
                *(float2*)(outp + (size_t)row * D_MODEL + col) =
                    make_float2(c[mt][nt][0] + bb.x, c[mt][nt][1] + bb.y);
                *(float2*)(outp + (size_t)(row + 8) * D_MODEL + col) =
                    make_float2(c[mt][nt][2] + bb.x, c[mt][nt][3] + bb.y);
            }
        }
    } else {
        // V: transposed store into g_vT[bh][d][s]
#pragma unroll
        for (int nt = 0; nt < 4; nt++) {
            const int col = n0 + wn*32 + nt*8 + 2*tig;
            const float2 bb = *(const float2*)(bias + col);
            const int hh = col >> 6;
            const int d0 = col & 63;
#pragma unroll
            for (int mt = 0; mt < 4; mt++) {
                const int row = m0 + wm*64 + mt*16 + gid;
                const int bidx = row >> 11;
                const int sidx = row & 2047;
                float* base = g_vT + ((size_t)(bidx*NUM_HEADS + hh) * D_HEAD + d0) * SEQ;
                base[sidx]            = c[mt][nt][0] + bb.x;
                base[SEQ + sidx]      = c[mt][nt][1] + bb.y;
                base[sidx + 8]        = c[mt][nt][2] + bb.x;
                base[SEQ + sidx + 8]  = c[mt][nt][3] + bb.y;
            }
        }
    }
}

// ============================================================
// Kernel 2 (tensor core): QEr[bh][s][j] = q_head[s,:] . Er[j,:]
// ============================================================
__global__ __launch_bounds__(256, 2)
void qer_tc_kernel(const float* __restrict__ Er)
{
    const int bh = blockIdx.z;
    const int b = bh >> 4, h = bh & 15;
    const int j0 = blockIdx.x * 128;
    const int s0 = blockIdx.y * 128;
    if (s0 + j0 + 254 < SEQ - 1) return;

    extern __shared__ float sm[];
    float* As = sm;
    float* Bs = sm + 2*128*GP;

    const int tid = threadIdx.x;
    const int wid = tid >> 5;
    const int lane = tid & 31;
    const int gid = lane >> 2;
    const int tig = lane & 3;
    const int wm = wid >> 2;
    const int wn = wid & 3;

    const float* Ag = g_q + ((size_t)b * SEQ + s0) * D_MODEL + (size_t)h * D_HEAD;
    const float* Bg = Er + (size_t)j0 * D_HEAD;

    float c[4][4][4];
#pragma unroll
    for (int mt = 0; mt < 4; mt++)
#pragma unroll
        for (int nt = 0; nt < 4; nt++)
#pragma unroll
            for (int r = 0; r < 4; r++) c[mt][nt][r] = 0.f;

    const int lrow = tid >> 3;
    const int lc4  = (tid & 7) * 4;

    float4 pa[4], pb[4];
#pragma unroll
    for (int i = 0; i < 4; i++) {
        pa[i] = *(const float4*)(Ag + (size_t)(lrow + i*32) * D_MODEL + lc4);
        pb[i] = *(const float4*)(Bg + (size_t)(lrow + i*32) * D_HEAD + lc4);
    }
#pragma unroll
    for (int i = 0; i < 4; i++) {
        float* da = As + (lrow + i*32) * GP + lc4;
        da[0]=f2tf_f(pa[i].x); da[1]=f2tf_f(pa[i].y); da[2]=f2tf_f(pa[i].z); da[3]=f2tf_f(pa[i].w);
        float* db = Bs + (lrow + i*32) * GP + lc4;
        db[0]=f2tf_f(pb[i].x); db[1]=f2tf_f(pb[i].y); db[2]=f2tf_f(pb[i].z); db[3]=f2tf_f(pb[i].w);
    }
    __syncthreads();

    for (int k0 = 0; k0 < D_HEAD; k0 += 32) {
        const int buf = (k0 >> 5) & 1;
        const bool has_next = (k0 + 32) < D_HEAD;
        if (has_next) {
#pragma unroll
            for (int i = 0; i < 4; i++) {
                pa[i] = *(const float4*)(Ag + (size_t)(lrow + i*32) * D_MODEL + k0 + 32 + lc4);
                pb[i] = *(const float4*)(Bg + (size_t)(lrow + i*32) * D_HEAD + k0 + 32 + lc4);
            }
        }
        const float* Ab = As + buf * 128 * GP;
        const float* Bb = Bs + buf * 128 * GP;
#pragma unroll
        for (int ks = 0; ks < 4; ks++) {
            const int kk = ks * 8;
            uint32_t a[4][4];
#pragma unroll
            for (int mt = 0; mt < 4; mt++) {
                const float* p = Ab + (wm*64 + mt*16 + gid) * GP + kk + tig;
                a[mt][0] = __float_as_uint(p[0]);
                a[mt][2] = __float_as_uint(p[4]);
                a[mt][1] = __float_as_uint(p[8*GP]);
                a[mt][3] = __float_as_uint(p[8*GP + 4]);
            }
#pragma unroll
            for (int nt = 0; nt < 4; nt++) {
                const float* q = Bb + (wn*32 + nt*8 + gid) * GP + kk + tig;
                uint32_t b0 = __float_as_uint(q[0]);
                uint32_t b1 = __float_as_uint(q[4]);
#pragma unroll
                for (int mt = 0; mt < 4; mt++)
                    mma_tf32(c[mt][nt][0], c[mt][nt][1], c[mt][nt][2], c[mt][nt][3],
                             a[mt][0], a[mt][1], a[mt][2], a[mt][3], b0, b1);
            }
        }
        if (has_next) {
            const int nb = buf ^ 1;
#pragma unroll
            for (int i = 0; i < 4; i++) {
                float* da = As + nb*128*GP + (lrow + i*32) * GP + lc4;
                da[0]=f2tf_f(pa[i].x); da[1]=f2tf_f(pa[i].y); da[2]=f2tf_f(pa[i].z); da[3]=f2tf_f(pa[i].w);
                float* db = Bs + nb*128*GP + (lrow + i*32) * GP + lc4;
                db[0]=f2tf_f(pb[i].x); db[1]=f2tf_f(pb[i].y); db[2]=f2tf_f(pb[i].z); db[3]=f2tf_f(pb[i].w);
            }
            __syncthreads();
        }
    }

    float* dst = g_qer + (size_t)bh * SEQ * SEQ;
#pragma unroll
    for (int nt = 0; nt < 4; nt++) {
        const int col = j0 + wn*32 + nt*8 + 2*tig;
#pragma unroll
        for (int mt = 0; mt < 4; mt++) {
            const int row = s0 + wm*64 + mt*16 + gid;
            *(float2*)(dst + (size_t)row * SEQ + col) = make_float2(c[mt][nt][0], c[mt][nt][1]);
            *(float2*)(dst + (size_t)(row + 8) * SEQ + col) = make_float2(c[mt][nt][2], c[mt][nt][3]);
        }
    }
}

// ============================================================
// Kernel 3 (tensor core): fused causal flash attention + rel bias.
// 8 warps x 16 rows; BK=64 keys/tile; tf32 mma for QK^T and PV.
// Rel-bias gathers seed the S accumulators directly.
// ============================================================
#define AQP 68
#define ATT_SMEM_FLOATS ((128 + 64 + 64 + 128) * AQP)
#define ATT_SMEM_BYTES (ATT_SMEM_FLOATS * 4)   // 104448 B

__global__ __launch_bounds__(256, 2)
void attn_tc_kernel(float* __restrict__ out)
{
    const int qt = gridDim.x - 1 - blockIdx.x;   // big tiles first
    const int bh = blockIdx.y;
    const int b = bh >> 4, h = bh & 15;
    const int s0 = qt * 128;

    extern __shared__ float smem[];
    float* qs = smem;                 // [128][AQP] tf32 Q (s, d)
    float* ks = qs + 128 * AQP;       // [64][AQP]  tf32 K (t, d)
    float* vT = ks + 64 * AQP;        // [64][AQP]  tf32 V^T (d, t)
    float* ps = vT + 64 * AQP;        // [128][AQP] tf32 P (s, t)

    const int tid = threadIdx.x;
    const int wid = tid >> 5;
    const int lane = tid & 31;
    const int gid = lane >> 2;
    const int tig = lane & 3;
    const int rb = wid * 16;
    const int r0 = rb + gid;
    const int r1 = r0 + 8;
    const int sg0 = s0 + r0;
    const int sg1 = s0 + r1;

    const float* qb  = g_q + ((size_t)b * SEQ + s0) * D_MODEL + (size_t)h * D_HEAD;
    const float* kb  = g_k + (size_t)b * SEQ * D_MODEL + (size_t)h * D_HEAD;
    const float* vtb = g_vT + (size_t)bh * D_HEAD * SEQ;
    const float* qr0 = g_qer + (size_t)bh * SEQ * SEQ + (size_t)sg0 * SEQ;
    const float* qr1 = g_qer + (size_t)bh * SEQ * SEQ + (size_t)sg1 * SEQ;

    // load Q tile (tf32)
#pragma unroll
    for (int i = 0; i < 8; i++) {
        int idx = tid + i * 256;
        int row = idx >> 4;
        int c4  = (idx & 15) * 4;
        float4 qv = *(const float4*)(qb + (size_t)row * D_MODEL + c4);
        *(float4*)(qs + row * AQP + c4) =
            make_float4(f2tf_f(qv.x), f2tf_f(qv.y), f2tf_f(qv.z), f2tf_f(qv.w));
    }

    float o[8][4];
#pragma unroll
    for (int nt = 0; nt < 8; nt++) { o[nt][0]=0.f; o[nt][1]=0.f; o[nt][2]=0.f; o[nt][3]=0.f; }
    float m0v = -1e30f, m1v = -1e30f, l0v = 0.f, l1v = 0.f;

    const int nkt = 2 * qt + 2;
    for (int kt = 0; kt < nkt; kt++) {
        const int t0 = kt * 64;

        // seed S accumulators with rel bias (clamped skew gather)
        float s_[8][4];
        {
            const int ja0 = 2047 + t0 + 2*tig - sg0;
            const int jb0 = 2047 + t0 + 2*tig - sg1;
#pragma unroll
            for (int nt = 0; nt < 8; nt++) {
                int ja = ja0 + nt*8, jb = ja + 1;
                int jc = jb0 + nt*8, jd = jc + 1;
                ja = ja > 2047 ? 2047 : ja;
                jb = jb > 2047 ? 2047 : jb;
                jc = jc > 2047 ? 2047 : jc;
                jd = jd > 2047 ? 2047 : jd;
                s_[nt][0] = qr0[ja];
                s_[nt][1] = qr0[jb];
                s_[nt][2] = qr1[jc];
                s_[nt][3] = qr1[jd];
            }
        }

        __syncthreads();   // previous ks/vT fully consumed

        // coop load K (t,d) and V^T (d,t), tf32
#pragma unroll
        for (int i = 0; i < 4; i++) {
            int idx = tid + i * 256;
            int row = idx >> 4;
            int c4  = (idx & 15) * 4;
            float4 kv = *(const float4*)(kb + (size_t)(t0 + row) * D_MODEL + c4);
            *(float4*)(ks + row * AQP + c4) =
                make_float4(f2tf_f(kv.x), f2tf_f(kv.y), f2tf_f(kv.z), f2tf_f(kv.w));
            float4 vv = *(const float4*)(vtb + (size_t)row * SEQ + t0 + c4);
            *(float4*)(vT + row * AQP + c4) =
                make_float4(f2tf_f(vv.x), f2tf_f(vv.y), f2tf_f(vv.z), f2tf_f(vv.w));
        }
        __syncthreads();

        // S += Q K^T
#pragma unroll
        for (int ks8 = 0; ks8 < 8; ks8++) {
            const int kk = ks8 * 8;
            const float* ap = qs + r0 * AQP + kk + tig;
            uint32_t a0 = __float_as_uint(ap[0]);
            uint32_t a1 = __float_as_uint(ap[8*AQP]);
            uint32_t a2 = __float_as_uint(ap[4]);
            uint32_t a3 = __float_as_uint(ap[8*AQP + 4]);
#pragma unroll
            for (int nt = 0; nt < 8; nt++) {
                const float* bp = ks + (nt*8 + gid) * AQP + kk + tig;
                uint32_t b0 = __float_as_uint(bp[0]);
                uint32_t b1 = __float_as_uint(bp[4]);
                mma_tf32(s_[nt][0], s_[nt][1], s_[nt][2], s_[nt][3],
                         a0, a1, a2, a3, b0, b1);
            }
        }

        // ---- online softmax, row half 0 (rows sg0) ----
        {
            float rmax = -1e30f;
#pragma unroll
            for (int nt = 0; nt < 8; nt++) {
                int tc = t0 + nt*8 + 2*tig;
                float v0 = s_[nt][0] * 0.125f;
                float v1 = s_[nt][1] * 0.125f;
                v0 = (tc     <= sg0) ? v0 : -1e30f;
                v1 = (tc + 1 <= sg0) ? v1 : -1e30f;
                s_[nt][0] = v0; s_[nt][1] = v1;
                rmax = fmaxf(rmax, fmaxf(v0, v1));
            }
            rmax = fmaxf(rmax, __shfl_xor_sync(0xffffffffu, rmax, 1));
            rmax = fmaxf(rmax, __shfl_xor_sync(0xffffffffu, rmax, 2));
            float mn = fmaxf(m0v, rmax);
            float alpha = __expf(m0v - mn);
            m0v = mn;
            float lsum = 0.f;
#pragma unroll
            for (int nt = 0; nt < 8; nt++) {
                float p0 = __expf(s_[nt][0] - mn);
                float p1 = __expf(s_[nt][1] - mn);
                lsum += p0 + p1;
                *(float2*)(ps + r0 * AQP + nt*8 + 2*tig) = make_float2(f2tf_f(p0), f2tf_f(p1));
                o[nt][0] *= alpha; o[nt][1] *= alpha;
            }
            lsum += __shfl_xor_sync(0xffffffffu, lsum, 1);
            lsum += __shfl_xor_sync(0xffffffffu, lsum, 2);
            l0v = l0v * alpha + lsum;
        }
        // ---- row half 1 (rows sg1) ----
        {
            float rmax = -1e30f;
#pragma unroll
            for (int nt = 0; nt < 8; nt++) {
                int tc = t0 + nt*8 + 2*tig;
                float v0 = s_[nt][2] * 0.125f;
                float v1 = s_[nt][3] * 0.125f;
                v0 = (tc     <= sg1) ? v0 : -1e30f;
                v1 = (tc + 1 <= sg1) ? v1 : -1e30f;
                s_[nt][2] = v0; s_[nt][3] = v1;
                rmax = fmaxf(rmax, fmaxf(v0, v1));
            }
            rmax = fmaxf(rmax, __shfl_xor_sync(0xffffffffu, rmax, 1));
            rmax = fmaxf(rmax, __shfl_xor_sync(0xffffffffu, rmax, 2));
            float mn = fmaxf(m1v, rmax);
            float alpha = __expf(m1v - mn);
            m1v = mn;
            float lsum = 0.f;
#pragma unroll
            for (int nt = 0; nt < 8; nt++) {
                float p0 = __expf(s_[nt][2] - mn);
                float p1 = __expf(s_[nt][3] - mn);
                lsum += p0 + p1;
                *(float2*)(ps + r1 * AQP + nt*8 + 2*tig) = make_float2(f2tf_f(p0), f2tf_f(p1));
                o[nt][2] *= alpha; o[nt][3] *= alpha;
            }
            lsum += __shfl_xor_sync(0xffffffffu, lsum, 1);
            lsum += __shfl_xor_sync(0xffffffffu, lsum, 2);
            l1v = l1v * alpha + lsum;
        }

        __syncwarp();   // P rows of this warp visible to this warp's lanes

        // O += P V   (A = P rows of this warp, B = V^T)
#pragma unroll
        for (int ks8 = 0; ks8 < 8; ks8++) {
            const int kk = ks8 * 8;
            const float* ap = ps + r0 * AQP + kk + tig;
            uint32_t a0 = __float_as_uint(ap[0]);
            uint32_t a1 = __float_as_uint(ap[8*AQP]);
            uint32_t a2 = __float_as_uint(ap[4]);
            uint32_t a3 = __float_as_uint(ap[8*AQP + 4]);
#pragma unroll
            for (int nt = 0; nt < 8; nt++) {
                const float* bp = vT + (nt*8 + gid) * AQP + kk + tig;
                uint32_t b0 = __float_as_uint(bp[0]);
                uint32_t b1 = __float_as_uint(bp[4]);
                mma_tf32(o[nt][0], o[nt][1], o[nt][2], o[nt][3],
                         a0, a1, a2, a3, b0, b1);
            }
        }
    }

    // epilogue: normalize and store
    const float inv0 = 1.f / l0v;
    const float inv1 = 1.f / l1v;
    float* ob = out + (size_t)b * SEQ * D_MODEL + (size_t)h * D_HEAD;
#pragma unroll
    for (int nt = 0; nt < 8; nt++) {
        const int d = nt*8 + 2*tig;
        *(float2*)(ob + (size_t)sg0 * D_MODEL + d) = make_float2(o[nt][0]*inv0, o[nt][1]*inv0);
        *(float2*)(ob + (size_t)sg1 * D_MODEL + d) = make_float2(o[nt][2]*inv1, o[nt][3]*inv1);
    }
}

// ============================================================
// launcher
// ============================================================
extern "C" void kernel_launch(void* const* d_in, const int* in_sizes, int n_in,
                              void* d_out, int out_size)
{
    const float* x  = (const float*)d_in[0];
    const float* Wq = (const float*)d_in[1];
    const float* bq = (const float*)d_in[2];
    const float* Wk = (const float*)d_in[3];
    const float* bk = (const float*)d_in[4];
    const float* Wv = (const float*)d_in[5];
    const float* bv = (const float*)d_in[6];
    const float* Er = (const float*)d_in[7];
    float* out = (float*)d_out;

    cudaFuncSetAttribute(qkv_tc_kernel, cudaFuncAttributeMaxDynamicSharedMemorySize,
                         GEMM_SMEM_BYTES);
    cudaFuncSetAttribute(qer_tc_kernel, cudaFuncAttributeMaxDynamicSharedMemorySize,
                         GEMM_SMEM_BYTES);
    cudaFuncSetAttribute(attn_tc_kernel, cudaFuncAttributeMaxDynamicSharedMemorySize,
                         ATT_SMEM_BYTES);

    dim3 g1(D_MODEL / 128, (BATCH * SEQ) / 128, 3);
    qkv_tc_kernel<<<g1, 256, GEMM_SMEM_BYTES>>>(x, Wq, bq, Wk, bk, Wv, bv);

    dim3 g2(SEQ / 128, SEQ / 128, BHN);
    qer_tc_kernel<<<g2, 256, GEMM_SMEM_BYTES>>>(Er);

    dim3 g3(SEQ / 128, BHN);
    attn_tc_kernel<<<g3, 256, ATT_SMEM_BYTES>>>(out);
}

// round 5
// speedup vs baseline: 2.6356x; 1.0628x over previous
#include <cuda_runtime.h>
#include <cuda_fp16.h>
#include <math.h>
#include <stdint.h>

#define D_MODEL 1024
#define NUM_HEADS 16
#define D_HEAD 64
#define BATCH 2
#define SEQ 2048
#define BHN (BATCH*NUM_HEADS)

// -------- scratch (static device memory; no runtime allocation) --------
__device__ float g_q[(size_t)BATCH*SEQ*D_MODEL];            // 16 MB
__device__ float g_k[(size_t)BATCH*SEQ*D_MODEL];            // 16 MB
__device__ float g_vT[(size_t)BHN*D_HEAD*SEQ];              // 16 MB, [bh][d][s]
__device__ __half g_qer[(size_t)BHN*SEQ*SEQ];               // 256 MB (fp16)

// ---------------- tf32 mma helpers ----------------
__device__ __forceinline__ uint32_t f2tf(float x) {
    uint32_t r;
    asm("cvt.rna.tf32.f32 %0, %1;" : "=r"(r) : "f"(x));
    return r;
}
__device__ __forceinline__ float f2tf_f(float x) {
    return __uint_as_float(f2tf(x));
}
__device__ __forceinline__ void mma_tf32(float& c0, float& c1, float& c2, float& c3,
                                         uint32_t a0, uint32_t a1, uint32_t a2, uint32_t a3,
                                         uint32_t b0, uint32_t b1) {
    asm volatile(
        "mma.sync.aligned.m16n8k8.row.col.f32.tf32.tf32.f32 "
        "{%0,%1,%2,%3}, {%4,%5,%6,%7}, {%8,%9}, {%0,%1,%2,%3};"
        : "+f"(c0), "+f"(c1), "+f"(c2), "+f"(c3)
        : "r"(a0), "r"(a1), "r"(a2), "r"(a3), "r"(b0), "r"(b1));
}

// smem geometry for tensor-core GEMMs: [2 buf][128 rows][36] floats each for A and B
#define GP 36
#define GEMM_SMEM_FLOATS (2*128*GP*2)
#define GEMM_SMEM_BYTES (GEMM_SMEM_FLOATS*4)

// ============================================================
// Kernel 1 (tensor core): Q/K/V projection.
// out[m,e] = sum_d x[m,d]*W[e,d] + b[e]; 128x128 tile, KC=32.
// z==2 (V) writes transposed into g_vT[bh][d][s].
// ============================================================
__global__ __launch_bounds__(256, 2)
void qkv_tc_kernel(const float* __restrict__ x,
                   const float* __restrict__ Wq, const float* __restrict__ bq,
                   const float* __restrict__ Wk, const float* __restrict__ bk,
                   const float* __restrict__ Wv, const float* __restrict__ bv)
{
    const float* W; const float* bias; float* outp;
    if (blockIdx.z == 0)      { W = Wq; bias = bq; outp = g_q; }
    else if (blockIdx.z == 1) { W = Wk; bias = bk; outp = g_k; }
    else                      { W = Wv; bias = bv; outp = nullptr; }

    extern __shared__ float sm[];
    float* As = sm;                 // [2][128][GP]
    float* Bs = sm + 2*128*GP;      // [2][128][GP]

    const int m0 = blockIdx.y * 128;
    const int n0 = blockIdx.x * 128;
    const int tid = threadIdx.x;
    const int wid = tid >> 5;
    const int lane = tid & 31;
    const int gid = lane >> 2;
    const int tig = lane & 3;
    const int wm = wid >> 2;
    const int wn = wid & 3;

    const float* Ag = x + (size_t)m0 * D_MODEL;
    const float* Bg = W + (size_t)n0 * D_MODEL;

    float c[4][4][4];
#pragma unroll
    for (int mt = 0; mt < 4; mt++)
#pragma unroll
        for (int nt = 0; nt < 4; nt++)
#pragma unroll
            for (int r = 0; r < 4; r++) c[mt][nt][r] = 0.f;

    const int lrow = tid >> 3;
    const int lc4  = (tid & 7) * 4;

    float4 pa[4], pb[4];
#pragma unroll
    for (int i = 0; i < 4; i++) {
        pa[i] = *(const float4*)(Ag + (size_t)(lrow + i*32) * D_MODEL + lc4);
        pb[i] = *(const float4*)(Bg + (size_t)(lrow + i*32) * D_MODEL + lc4);
    }
#pragma unroll
    for (int i = 0; i < 4; i++) {
        float* da = As + (lrow + i*32) * GP + lc4;
        da[0]=f2tf_f(pa[i].x); da[1]=f2tf_f(pa[i].y); da[2]=f2tf_f(pa[i].z); da[3]=f2tf_f(pa[i].w);
        float* db = Bs + (lrow + i*32) * GP + lc4;
        db[0]=f2tf_f(pb[i].x); db[1]=f2tf_f(pb[i].y); db[2]=f2tf_f(pb[i].z); db[3]=f2tf_f(pb[i].w);
    }
    __syncthreads();

    for (int k0 = 0; k0 < D_MODEL; k0 += 32) {
        const int buf = (k0 >> 5) & 1;
        const bool has_next = (k0 + 32) < D_MODEL;
        if (has_next) {
#pragma unroll
            for (int i = 0; i < 4; i++) {
                pa[i] = *(const float4*)(Ag + (size_t)(lrow + i*32) * D_MODEL + k0 + 32 + lc4);
                pb[i] = *(const float4*)(Bg + (size_t)(lrow + i*32) * D_MODEL + k0 + 32 + lc4);
            }
        }
        const float* Ab = As + buf * 128 * GP;
        const float* Bb = Bs + buf * 128 * GP;
#pragma unroll
        for (int ks = 0; ks < 4; ks++) {
            const int kk = ks * 8;
            uint32_t a[4][4];
#pragma unroll
            for (int mt = 0; mt < 4; mt++) {
                const float* p = Ab + (wm*64 + mt*16 + gid) * GP + kk + tig;
                a[mt][0] = __float_as_uint(p[0]);
                a[mt][2] = __float_as_uint(p[4]);
                a[mt][1] = __float_as_uint(p[8*GP]);
                a[mt][3] = __float_as_uint(p[8*GP + 4]);
            }
#pragma unroll
            for (int nt = 0; nt < 4; nt++) {
                const float* q = Bb + (wn*32 + nt*8 + gid) * GP + kk + tig;
                uint32_t b0 = __float_as_uint(q[0]);
                uint32_t b1 = __float_as_uint(q[4]);
#pragma unroll
                for (int mt = 0; mt < 4; mt++)
                    mma_tf32(c[mt][nt][0], c[mt][nt][1], c[mt][nt][2], c[mt][nt][3],
                             a[mt][0], a[mt][1], a[mt][2], a[mt][3], b0, b1);
            }
        }
        if (has_next) {
            const int nb = buf ^ 1;
#pragma unroll
            for (int i = 0; i < 4; i++) {
                float* da = As + nb*128*GP + (lrow + i*32) * GP + lc4;
                da[0]=f2tf_f(pa[i].x); da[1]=f2tf_f(pa[i].y); da[2]=f2tf_f(pa[i].z); da[3]=f2tf_f(pa[i].w);
                float* db = Bs + nb*128*GP + (lrow + i*32) * GP + lc4;
                db[0]=f2tf_f(pb[i].x); db[1]=f2tf_f(pb[i].y); db[2]=f2tf_f(pb[i].z); db[3]=f2tf_f(pb[i].w);
            }
            __syncthreads();
        }
    }

    if (blockIdx.z != 2) {
        // row-major store with bias
#pragma unroll
        for (int nt = 0; nt < 4; nt++) {
            const int col = n0 + wn*32 + nt*8 + 2*tig;
            const float2 bb = *(const float2*)(bias + col);
#pragma unroll
            for (int mt = 0; mt < 4; mt++) {
                const int row = m0 + wm*64 + mt*16 + gid;
                *(float2*)(outp + (size_t)row * D_MODEL + col) =
                    make_float2(c[mt][nt][0] + bb.x, c[mt][nt][1] + bb.y);
                *(float2*)(outp + (size_t)(row + 8) * D_MODEL + col) =
                    make_float2(c[mt][nt][2] + bb.x, c[mt][nt][3] + bb.y);
            }
        }
    } else {
        // V: transposed store into g_vT[bh][d][s]
#pragma unroll
        for (int nt = 0; nt < 4; nt++) {
            const int col = n0 + wn*32 + nt*8 + 2*tig;
            const float2 bb = *(const float2*)(bias + col);
            const int hh = col >> 6;
            const int d0 = col & 63;
#pragma unroll
            for (int mt = 0; mt < 4; mt++) {
                const int row = m0 + wm*64 + mt*16 + gid;
                const int bidx = row >> 11;
                const int sidx = row & 2047;
                float* base = g_vT + ((size_t)(bidx*NUM_HEADS + hh) * D_HEAD + d0) * SEQ;
                base[sidx]            = c[mt][nt][0] + bb.x;
                base[SEQ + sidx]      = c[mt][nt][1] + bb.y;
                base[sidx + 8]        = c[mt][nt][2] + bb.x;
                base[SEQ + sidx + 8]  = c[mt][nt][3] + bb.y;
            }
        }
    }
}

// ============================================================
// Kernel 2 (tensor core): QEr[bh][s][j] = q_head[s,:] . Er[j,:]
// fp16 output (half2 stores).
// ============================================================
__global__ __launch_bounds__(256, 2)
void qer_tc_kernel(const float* __restrict__ Er)
{
    const int bh = blockIdx.z;
    const int b = bh >> 4, h = bh & 15;
    const int j0 = blockIdx.x * 128;
    const int s0 = blockIdx.y * 128;
    if (s0 + j0 + 254 < SEQ - 1) return;

    extern __shared__ float sm[];
    float* As = sm;
    float* Bs = sm + 2*128*GP;

    const int tid = threadIdx.x;
    const int wid = tid >> 5;
    const int lane = tid & 31;
    const int gid = lane >> 2;
    const int tig = lane & 3;
    const int wm = wid >> 2;
    const int wn = wid & 3;

    const float* Ag = g_q + ((size_t)b * SEQ + s0) * D_MODEL + (size_t)h * D_HEAD;
    const float* Bg = Er + (size_t)j0 * D_HEAD;

    float c[4][4][4];
#pragma unroll
    for (int mt = 0; mt < 4; mt++)
#pragma unroll
        for (int nt = 0; nt < 4; nt++)
#pragma unroll
            for (int r = 0; r < 4; r++) c[mt][nt][r] = 0.f;

    const int lrow = tid >> 3;
    const int lc4  = (tid & 7) * 4;

    float4 pa[4], pb[4];
#pragma unroll
    for (int i = 0; i < 4; i++) {
        pa[i] = *(const float4*)(Ag + (size_t)(lrow + i*32) * D_MODEL + lc4);
        pb[i] = *(const float4*)(Bg + (size_t)(lrow + i*32) * D_HEAD + lc4);
    }
#pragma unroll
    for (int i = 0; i < 4; i++) {
        float* da = As + (lrow + i*32) * GP + lc4;
        da[0]=f2tf_f(pa[i].x); da[1]=f2tf_f(pa[i].y); da[2]=f2tf_f(pa[i].z); da[3]=f2tf_f(pa[i].w);
        float* db = Bs + (lrow + i*32) * GP + lc4;
        db[0]=f2tf_f(pb[i].x); db[1]=f2tf_f(pb[i].y); db[2]=f2tf_f(pb[i].z); db[3]=f2tf_f(pb[i].w);
    }
    __syncthreads();

    for (int k0 = 0; k0 < D_HEAD; k0 += 32) {
        const int buf = (k0 >> 5) & 1;
        const bool has_next = (k0 + 32) < D_HEAD;
        if (has_next) {
#pragma unroll
            for (int i = 0; i < 4; i++) {
                pa[i] = *(const float4*)(Ag + (size_t)(lrow + i*32) * D_MODEL + k0 + 32 + lc4);
                pb[i] = *(const float4*)(Bg + (size_t)(lrow + i*32) * D_HEAD + k0 + 32 + lc4);
            }
        }
        const float* Ab = As + buf * 128 * GP;
        const float* Bb = Bs + buf * 128 * GP;
#pragma unroll
        for (int ks = 0; ks < 4; ks++) {
            const int kk = ks * 8;
            uint32_t a[4][4];
#pragma unroll
            for (int mt = 0; mt < 4; mt++) {
                const float* p = Ab + (wm*64 + mt*16 + gid) * GP + kk + tig;
                a[mt][0] = __float_as_uint(p[0]);
                a[mt][2] = __float_as_uint(p[4]);
                a[mt][1] = __float_as_uint(p[8*GP]);
                a[mt][3] = __float_as_uint(p[8*GP + 4]);
            }
#pragma unroll
            for (int nt = 0; nt < 4; nt++) {
                const float* q = Bb + (wn*32 + nt*8 + gid) * GP + kk + tig;
                uint32_t b0 = __float_as_uint(q[0]);
                uint32_t b1 = __float_as_uint(q[4]);
#pragma unroll
                for (int mt = 0; mt < 4; mt++)
                    mma_tf32(c[mt][nt][0], c[mt][nt][1], c[mt][nt][2], c[mt][nt][3],
                             a[mt][0], a[mt][1], a[mt][2], a[mt][3], b0, b1);
            }
        }
        if (has_next) {
            const int nb = buf ^ 1;
#pragma unroll
            for (int i = 0; i < 4; i++) {
                float* da = As + nb*128*GP + (lrow + i*32) * GP + lc4;
                da[0]=f2tf_f(pa[i].x); da[1]=f2tf_f(pa[i].y); da[2]=f2tf_f(pa[i].z); da[3]=f2tf_f(pa[i].w);
                float* db = Bs + nb*128*GP + (lrow + i*32) * GP + lc4;
                db[0]=f2tf_f(pb[i].x); db[1]=f2tf_f(pb[i].y); db[2]=f2tf_f(pb[i].z); db[3]=f2tf_f(pb[i].w);
            }
            __syncthreads();
        }
    }

    __half* dst = g_qer + (size_t)bh * SEQ * SEQ;
#pragma unroll
    for (int nt = 0; nt < 4; nt++) {
        const int col = j0 + wn*32 + nt*8 + 2*tig;   // even
#pragma unroll
        for (int mt = 0; mt < 4; mt++) {
            const int row = s0 + wm*64 + mt*16 + gid;
            *(__half2*)(dst + (size_t)row * SEQ + col) =
                __floats2half2_rn(c[mt][nt][0], c[mt][nt][1]);
            *(__half2*)(dst + (size_t)(row + 8) * SEQ + col) =
                __floats2half2_rn(c[mt][nt][2], c[mt][nt][3]);
        }
    }
}

// ============================================================
// Kernel 3 (tensor core): fused causal flash attention + rel bias.
// 8 warps x 16 rows; BK=64 keys/tile; tf32 mma for QK^T and PV.
// Rel-bias gathers (fp16) seed the S accumulators directly.
// ============================================================
#define AQP 68
#define ATT_SMEM_FLOATS ((128 + 64 + 64 + 128) * AQP)
#define ATT_SMEM_BYTES (ATT_SMEM_FLOATS * 4)   // 104448 B

__global__ __launch_bounds__(256, 2)
void attn_tc_kernel(float* __restrict__ out)
{
    const int qt = gridDim.x - 1 - blockIdx.x;   // big tiles first
    const int bh = blockIdx.y;
    const int b = bh >> 4, h = bh & 15;
    const int s0 = qt * 128;

    extern __shared__ float smem[];
    float* qs = smem;                 // [128][AQP] tf32 Q (s, d)
    float* ks = qs + 128 * AQP;       // [64][AQP]  tf32 K (t, d)
    float* vT = ks + 64 * AQP;        // [64][AQP]  tf32 V^T (d, t)
    float* ps = vT + 64 * AQP;        // [128][AQP] tf32 P (s, t)

    const int tid = threadIdx.x;
    const int wid = tid >> 5;
    const int lane = tid & 31;
    const int gid = lane >> 2;
    const int tig = lane & 3;
    const int rb = wid * 16;
    const int r0 = rb + gid;
    const int r1 = r0 + 8;
    const int sg0 = s0 + r0;
    const int sg1 = s0 + r1;

    const float* qb  = g_q + ((size_t)b * SEQ + s0) * D_MODEL + (size_t)h * D_HEAD;
    const float* kb  = g_k + (size_t)b * SEQ * D_MODEL + (size_t)h * D_HEAD;
    const float* vtb = g_vT + (size_t)bh * D_HEAD * SEQ;
    const __half* qr0 = g_qer + (size_t)bh * SEQ * SEQ + (size_t)sg0 * SEQ;
    const __half* qr1 = g_qer + (size_t)bh * SEQ * SEQ + (size_t)sg1 * SEQ;

    // load Q tile (tf32)
#pragma unroll
    for (int i = 0; i < 8; i++) {
        int idx = tid + i * 256;
        int row = idx >> 4;
        int c4  = (idx & 15) * 4;
        float4 qv = *(const float4*)(qb + (size_t)row * D_MODEL + c4);
        *(float4*)(qs + row * AQP + c4) =
            make_float4(f2tf_f(qv.x), f2tf_f(qv.y), f2tf_f(qv.z), f2tf_f(qv.w));
    }

    float o[8][4];
#pragma unroll
    for (int nt = 0; nt < 8; nt++) { o[nt][0]=0.f; o[nt][1]=0.f; o[nt][2]=0.f; o[nt][3]=0.f; }
    float m0v = -1e30f, m1v = -1e30f, l0v = 0.f, l1v = 0.f;

    const int nkt = 2 * qt + 2;
    for (int kt = 0; kt < nkt; kt++) {
        const int t0 = kt * 64;

        // seed S accumulators with rel bias (clamped skew gather, fp16)
        float s_[8][4];
        {
            const int ja0 = 2047 + t0 + 2*tig - sg0;
            const int jb0 = 2047 + t0 + 2*tig - sg1;
#pragma unroll
            for (int nt = 0; nt < 8; nt++) {
                int ja = ja0 + nt*8, jb = ja + 1;
                int jc = jb0 + nt*8, jd = jc + 1;
                ja = ja > 2047 ? 2047 : ja;
                jb = jb > 2047 ? 2047 : jb;
                jc = jc > 2047 ? 2047 : jc;
                jd = jd > 2047 ? 2047 : jd;
                s_[nt][0] = __half2float(qr0[ja]);
                s_[nt][1] = __half2float(qr0[jb]);
                s_[nt][2] = __half2float(qr1[jc]);
                s_[nt][3] = __half2float(qr1[jd]);
            }
        }

        __syncthreads();   // previous ks/vT fully consumed

        // coop load K (t,d) and V^T (d,t), tf32
#pragma unroll
        for (int i = 0; i < 4; i++) {
            int idx = tid + i * 256;
            int row = idx >> 4;
            int c4  = (idx & 15) * 4;
            float4 kv = *(const float4*)(kb + (size_t)(t0 + row) * D_MODEL + c4);
            *(float4*)(ks + row * AQP + c4) =
                make_float4(f2tf_f(kv.x), f2tf_f(kv.y), f2tf_f(kv.z), f2tf_f(kv.w));
            float4 vv = *(const float4*)(vtb + (size_t)row * SEQ + t0 + c4);
            *(float4*)(vT + row * AQP + c4) =
                make_float4(f2tf_f(vv.x), f2tf_f(vv.y), f2tf_f(vv.z), f2tf_f(vv.w));
        }
        __syncthreads();

        // S += Q K^T
#pragma unroll
        for (int ks8 = 0; ks8 < 8; ks8++) {
            const int kk = ks8 * 8;
            const float* ap = qs + r0 * AQP + kk + tig;
            uint32_t a0 = __float_as_uint(ap[0]);
            uint32_t a1 = __float_as_uint(ap[8*AQP]);
            uint32_t a2 = __float_as_uint(ap[4]);
            uint32_t a3 = __float_as_uint(ap[8*AQP + 4]);
#pragma unroll
            for (int nt = 0; nt < 8; nt++) {
                const float* bp = ks + (nt*8 + gid) * AQP + kk + tig;
                uint32_t b0 = __float_as_uint(bp[0]);
                uint32_t b1 = __float_as_uint(bp[4]);
                mma_tf32(s_[nt][0], s_[nt][1], s_[nt][2], s_[nt][3],
                         a0, a1, a2, a3, b0, b1);
            }
        }

        // ---- online softmax, row half 0 (rows sg0) ----
        {
            float rmax = -1e30f;
#pragma unroll
            for (int nt = 0; nt < 8; nt++) {
                int tc = t0 + nt*8 + 2*tig;
                float v0 = s_[nt][0] * 0.125f;
                float v1 = s_[nt][1] * 0.125f;
                v0 = (tc     <= sg0) ? v0 : -1e30f;
                v1 = (tc + 1 <= sg0) ? v1 : -1e30f;
                s_[nt][0] = v0; s_[nt][1] = v1;
                rmax = fmaxf(rmax, fmaxf(v0, v1));
            }
            rmax = fmaxf(rmax, __shfl_xor_sync(0xffffffffu, rmax, 1));
            rmax = fmaxf(rmax, __shfl_xor_sync(0xffffffffu, rmax, 2));
            float mn = fmaxf(m0v, rmax);
            float alpha = __expf(m0v - mn);
            m0v = mn;
            float lsum = 0.f;
#pragma unroll
            for (int nt = 0; nt < 8; nt++) {
                float p0 = __expf(s_[nt][0] - mn);
                float p1 = __expf(s_[nt][1] - mn);
                lsum += p0 + p1;
                *(float2*)(ps + r0 * AQP + nt*8 + 2*tig) = make_float2(f2tf_f(p0), f2tf_f(p1));
                o[nt][0] *= alpha; o[nt][1] *= alpha;
            }
            lsum += __shfl_xor_sync(0xffffffffu, lsum, 1);
            lsum += __shfl_xor_sync(0xffffffffu, lsum, 2);
            l0v = l0v * alpha + lsum;
        }
        // ---- row half 1 (rows sg1) ----
        {
            float rmax = -1e30f;
#pragma unroll
            for (int nt = 0; nt < 8; nt++) {
                int tc = t0 + nt*8 + 2*tig;
                float v0 = s_[nt][2] * 0.125f;
                float v1 = s_[nt][3] * 0.125f;
                v0 = (tc     <= sg1) ? v0 : -1e30f;
                v1 = (tc + 1 <= sg1) ? v1 : -1e30f;
                s_[nt][2] = v0; s_[nt][3] = v1;
                rmax = fmaxf(rmax, fmaxf(v0, v1));
            }
            rmax = fmaxf(rmax, __shfl_xor_sync(0xffffffffu, rmax, 1));
            rmax = fmaxf(rmax, __shfl_xor_sync(0xffffffffu, rmax, 2));
            float mn = fmaxf(m1v, rmax);
            float alpha = __expf(m1v - mn);
            m1v = mn;
            float lsum = 0.f;
#pragma unroll
            for (int nt = 0; nt < 8; nt++) {
                float p0 = __expf(s_[nt][2] - mn);
                float p1 = __expf(s_[nt][3] - mn);
                lsum += p0 + p1;
                *(float2*)(ps + r1 * AQP + nt*8 + 2*tig) = make_float2(f2tf_f(p0), f2tf_f(p1));
                o[nt][2] *= alpha; o[nt][3] *= alpha;
            }
            lsum += __shfl_xor_sync(0xffffffffu, lsum, 1);
            lsum += __shfl_xor_sync(0xffffffffu, lsum, 2);
            l1v = l1v * alpha + lsum;
        }

        __syncwarp();   // P rows of this warp visible to this warp's lanes

        // O += P V   (A = P rows of this warp, B = V^T)
#pragma unroll
        for (int ks8 = 0; ks8 < 8; ks8++) {
            const int kk = ks8 * 8;
            const float* ap = ps + r0 * AQP + kk + tig;
            uint32_t a0 = __float_as_uint(ap[0]);
            uint32_t a1 = __float_as_uint(ap[8*AQP]);
            uint32_t a2 = __float_as_uint(ap[4]);
            uint32_t a3 = __float_as_uint(ap[8*AQP + 4]);
#pragma unroll
            for (int nt = 0; nt < 8; nt++) {
                const float* bp = vT + (nt*8 + gid) * AQP + kk + tig;
                uint32_t b0 = __float_as_uint(bp[0]);
                uint32_t b1 = __float_as_uint(bp[4]);
                mma_tf32(o[nt][0], o[nt][1], o[nt][2], o[nt][3],
                         a0, a1, a2, a3, b0, b1);
            }
        }
    }

    // epilogue: normalize and store
    const float inv0 = 1.f / l0v;
    const float inv1 = 1.f / l1v;
    float* ob = out + (size_t)b * SEQ * D_MODEL + (size_t)h * D_HEAD;
#pragma unroll
    for (int nt = 0; nt < 8; nt++) {
        const int d = nt*8 + 2*tig;
        *(float2*)(ob + (size_t)sg0 * D_MODEL + d) = make_float2(o[nt][0]*inv0, o[nt][1]*inv0);
        *(float2*)(ob + (size_t)sg1 * D_MODEL + d) = make_float2(o[nt][2]*inv1, o[nt][3]*inv1);
    }
}

// ============================================================
// launcher
// ============================================================
extern "C" void kernel_launch(void* const* d_in, const int* in_sizes, int n_in,
                              void* d_out, int out_size)
{
    const float* x  = (const float*)d_in[0];
    const float* Wq = (const float*)d_in[1];
    const float* bq = (const float*)d_in[2];
    const float* Wk = (const float*)d_in[3];
    const float* bk = (const float*)d_in[4];
    const float* Wv = (const float*)d_in[5];
    const float* bv = (const float*)d_in[6];
    const float* Er = (const float*)d_in[7];
    float* out = (float*)d_out;

    cudaFuncSetAttribute(qkv_tc_kernel, cudaFuncAttributeMaxDynamicSharedMemorySize,
                         GEMM_SMEM_BYTES);
    cudaFuncSetAttribute(qer_tc_kernel, cudaFuncAttributeMaxDynamicSharedMemorySize,
                         GEMM_SMEM_BYTES);
    cudaFuncSetAttribute(attn_tc_kernel, cudaFuncAttributeMaxDynamicSharedMemorySize,
                         ATT_SMEM_BYTES);

    dim3 g1(D_MODEL / 128, (BATCH * SEQ) / 128, 3);
    qkv_tc_kernel<<<g1, 256, GEMM_SMEM_BYTES>>>(x, Wq, bq, Wk, bk, Wv, bv);

    dim3 g2(SEQ / 128, SEQ / 128, BHN);
    qer_tc_kernel<<<g2, 256, GEMM_SMEM_BYTES>>>(Er);

    dim3 g3(SEQ / 128, BHN);
    attn_tc_kernel<<<g3, 256, ATT_SMEM_BYTES>>>(out);
}

// round 6
// speedup vs baseline: 3.2028x; 1.2152x over previous
#include <cuda_runtime.h>
#include <cuda_fp16.h>
#include <math.h>
#include <stdint.h>

#define D_MODEL 1024
#define NUM_HEADS 16
#define D_HEAD 64
#define BATCH 2
#define SEQ 2048
#define BHN (BATCH*NUM_HEADS)

// -------- scratch (static device memory; no runtime allocation) --------
__device__ float  g_q  [(size_t)BATCH*SEQ*D_MODEL];          // 16 MB fp32
__device__ __half g_k  [(size_t)BATCH*SEQ*D_MODEL];          // 8 MB fp16
__device__ __half g_vT [(size_t)BHN*D_HEAD*SEQ];             // 8 MB fp16, [bh][d][s]
__device__ __half g_qer[(size_t)BHN*SEQ*SEQ];                // 256 MB fp16

// ---------------- mma helpers ----------------
__device__ __forceinline__ uint32_t f2tf(float x) {
    uint32_t r;
    asm("cvt.rna.tf32.f32 %0, %1;" : "=r"(r) : "f"(x));
    return r;
}
__device__ __forceinline__ float f2tf_f(float x) {
    return __uint_as_float(f2tf(x));
}
__device__ __forceinline__ void mma_tf32(float& c0, float& c1, float& c2, float& c3,
                                         uint32_t a0, uint32_t a1, uint32_t a2, uint32_t a3,
                                         uint32_t b0, uint32_t b1) {
    asm volatile(
        "mma.sync.aligned.m16n8k8.row.col.f32.tf32.tf32.f32 "
        "{%0,%1,%2,%3}, {%4,%5,%6,%7}, {%8,%9}, {%0,%1,%2,%3};"
        : "+f"(c0), "+f"(c1), "+f"(c2), "+f"(c3)
        : "r"(a0), "r"(a1), "r"(a2), "r"(a3), "r"(b0), "r"(b1));
}
__device__ __forceinline__ void mma_f16(float& c0, float& c1, float& c2, float& c3,
                                        uint32_t a0, uint32_t a1, uint32_t a2, uint32_t a3,
                                        uint32_t b0, uint32_t b1) {
    asm volatile(
        "mma.sync.aligned.m16n8k16.row.col.f32.f16.f16.f32 "
        "{%0,%1,%2,%3}, {%4,%5,%6,%7}, {%8,%9}, {%0,%1,%2,%3};"
        : "+f"(c0), "+f"(c1), "+f"(c2), "+f"(c3)
        : "r"(a0), "r"(a1), "r"(a2), "r"(a3), "r"(b0), "r"(b1));
}
__device__ __forceinline__ uint32_t pack_h2(float x, float y) {
    __half2 h = __floats2half2_rn(x, y);
    return *(uint32_t*)&h;
}
__device__ __forceinline__ void cp_async16(uint32_t saddr, const void* g) {
    asm volatile("cp.async.cg.shared.global [%0], [%1], 16;" :: "r"(saddr), "l"(g));
}
#define CP_COMMIT() asm volatile("cp.async.commit_group;")
#define CP_WAIT0()  asm volatile("cp.async.wait_group 0;")

// smem geometry for tensor-core GEMMs: [2 buf][128 rows][36] floats each for A and B
#define GP 36
#define GEMM_SMEM_FLOATS (2*128*GP*2)
#define GEMM_SMEM_BYTES (GEMM_SMEM_FLOATS*4)

// ============================================================
// Kernel 1 (tensor core): Q/K/V projection.
// z==0 -> g_q fp32; z==1 -> g_k fp16; z==2 -> g_vT fp16 transposed.
// ============================================================
__global__ __launch_bounds__(256, 2)
void qkv_tc_kernel(const float* __restrict__ x,
                   const float* __restrict__ Wq, const float* __restrict__ bq,
                   const float* __restrict__ Wk, const float* __restrict__ bk,
                   const float* __restrict__ Wv, const float* __restrict__ bv)
{
    const float* W; const float* bias;
    if (blockIdx.z == 0)      { W = Wq; bias = bq; }
    else if (blockIdx.z == 1) { W = Wk; bias = bk; }
    else                      { W = Wv; bias = bv; }

    extern __shared__ float sm[];
    float* As = sm;                 // [2][128][GP]
    float* Bs = sm + 2*128*GP;      // [2][128][GP]

    const int m0 = blockIdx.y * 128;
    const int n0 = blockIdx.x * 128;
    const int tid = threadIdx.x;
    const int wid = tid >> 5;
    const int lane = tid & 31;
    const int gid = lane >> 2;
    const int tig = lane & 3;
    const int wm = wid >> 2;
    const int wn = wid & 3;

    const float* Ag = x + (size_t)m0 * D_MODEL;
    const float* Bg = W + (size_t)n0 * D_MODEL;

    float c[4][4][4];
#pragma unroll
    for (int mt = 0; mt < 4; mt++)
#pragma unroll
        for (int nt = 0; nt < 4; nt++)
#pragma unroll
            for (int r = 0; r < 4; r++) c[mt][nt][r] = 0.f;

    const int lrow = tid >> 3;
    const int lc4  = (tid & 7) * 4;

    float4 pa[4], pb[4];
#pragma unroll
    for (int i = 0; i < 4; i++) {
        pa[i] = *(const float4*)(Ag + (size_t)(lrow + i*32) * D_MODEL + lc4);
        pb[i] = *(const float4*)(Bg + (size_t)(lrow + i*32) * D_MODEL + lc4);
    }
#pragma unroll
    for (int i = 0; i < 4; i++) {
        float* da = As + (lrow + i*32) * GP + lc4;
        da[0]=f2tf_f(pa[i].x); da[1]=f2tf_f(pa[i].y); da[2]=f2tf_f(pa[i].z); da[3]=f2tf_f(pa[i].w);
        float* db = Bs + (lrow + i*32) * GP + lc4;
        db[0]=f2tf_f(pb[i].x); db[1]=f2tf_f(pb[i].y); db[2]=f2tf_f(pb[i].z); db[3]=f2tf_f(pb[i].w);
    }
    __syncthreads();

    for (int k0 = 0; k0 < D_MODEL; k0 += 32) {
        const int buf = (k0 >> 5) & 1;
        const bool has_next = (k0 + 32) < D_MODEL;
        if (has_next) {
#pragma unroll
            for (int i = 0; i < 4; i++) {
                pa[i] = *(const float4*)(Ag + (size_t)(lrow + i*32) * D_MODEL + k0 + 32 + lc4);
                pb[i] = *(const float4*)(Bg + (size_t)(lrow + i*32) * D_MODEL + k0 + 32 + lc4);
            }
        }
        const float* Ab = As + buf * 128 * GP;
        const float* Bb = Bs + buf * 128 * GP;
#pragma unroll
        for (int ks = 0; ks < 4; ks++) {
            const int kk = ks * 8;
            uint32_t a[4][4];
#pragma unroll
            for (int mt = 0; mt < 4; mt++) {
                const float* p = Ab + (wm*64 + mt*16 + gid) * GP + kk + tig;
                a[mt][0] = __float_as_uint(p[0]);
                a[mt][2] = __float_as_uint(p[4]);
                a[mt][1] = __float_as_uint(p[8*GP]);
                a[mt][3] = __float_as_uint(p[8*GP + 4]);
            }
#pragma unroll
            for (int nt = 0; nt < 4; nt++) {
                const float* q = Bb + (wn*32 + nt*8 + gid) * GP + kk + tig;
                uint32_t b0 = __float_as_uint(q[0]);
                uint32_t b1 = __float_as_uint(q[4]);
#pragma unroll
                for (int mt = 0; mt < 4; mt++)
                    mma_tf32(c[mt][nt][0], c[mt][nt][1], c[mt][nt][2], c[mt][nt][3],
                             a[mt][0], a[mt][1], a[mt][2], a[mt][3], b0, b1);
            }
        }
        if (has_next) {
            const int nb = buf ^ 1;
#pragma unroll
            for (int i = 0; i < 4; i++) {
                float* da = As + nb*128*GP + (lrow + i*32) * GP + lc4;
                da[0]=f2tf_f(pa[i].x); da[1]=f2tf_f(pa[i].y); da[2]=f2tf_f(pa[i].z); da[3]=f2tf_f(pa[i].w);
                float* db = Bs + nb*128*GP + (lrow + i*32) * GP + lc4;
                db[0]=f2tf_f(pb[i].x); db[1]=f2tf_f(pb[i].y); db[2]=f2tf_f(pb[i].z); db[3]=f2tf_f(pb[i].w);
            }
            __syncthreads();
        }
    }

    if (blockIdx.z == 0) {
        // Q: fp32 row-major store with bias
#pragma unroll
        for (int nt = 0; nt < 4; nt++) {
            const int col = n0 + wn*32 + nt*8 + 2*tig;
            const float2 bb = *(const float2*)(bias + col);
#pragma unroll
            for (int mt = 0; mt < 4; mt++) {
                const int row = m0 + wm*64 + mt*16 + gid;
                *(float2*)(g_q + (size_t)row * D_MODEL + col) =
                    make_float2(c[mt][nt][0] + bb.x, c[mt][nt][1] + bb.y);
                *(float2*)(g_q + (size_t)(row + 8) * D_MODEL + col) =
                    make_float2(c[mt][nt][2] + bb.x, c[mt][nt][3] + bb.y);
            }
        }
    } else if (blockIdx.z == 1) {
        // K: fp16 row-major store
#pragma unroll
        for (int nt = 0; nt < 4; nt++) {
            const int col = n0 + wn*32 + nt*8 + 2*tig;   // even
            const float2 bb = *(const float2*)(bias + col);
#pragma unroll
            for (int mt = 0; mt < 4; mt++) {
                const int row = m0 + wm*64 + mt*16 + gid;
                *(__half2*)(g_k + (size_t)row * D_MODEL + col) =
                    __floats2half2_rn(c[mt][nt][0] + bb.x, c[mt][nt][1] + bb.y);
                *(__half2*)(g_k + (size_t)(row + 8) * D_MODEL + col) =
                    __floats2half2_rn(c[mt][nt][2] + bb.x, c[mt][nt][3] + bb.y);
            }
        }
    } else {
        // V: fp16 transposed store into g_vT[bh][d][s]
#pragma unroll
        for (int nt = 0; nt < 4; nt++) {
            const int col = n0 + wn*32 + nt*8 + 2*tig;
            const float2 bb = *(const float2*)(bias + col);
            const int hh = col >> 6;
            const int d0 = col & 63;
#pragma unroll
            for (int mt = 0; mt < 4; mt++) {
                const int row = m0 + wm*64 + mt*16 + gid;
                const int bidx = row >> 11;
                const int sidx = row & 2047;
                __half* base = g_vT + ((size_t)(bidx*NUM_HEADS + hh) * D_HEAD + d0) * SEQ;
                base[sidx]            = __float2half(c[mt][nt][0] + bb.x);
                base[SEQ + sidx]      = __float2half(c[mt][nt][1] + bb.y);
                base[sidx + 8]        = __float2half(c[mt][nt][2] + bb.x);
                base[SEQ + sidx + 8]  = __float2half(c[mt][nt][3] + bb.y);
            }
        }
    }
}

// ============================================================
// Kernel 2 (tensor core): QEr[bh][s][j] = q_head[s,:] . Er[j,:]
// fp16 output.
// ============================================================
__global__ __launch_bounds__(256, 2)
void qer_tc_kernel(const float* __restrict__ Er)
{
    const int bh = blockIdx.z;
    const int b = bh >> 4, h = bh & 15;
    const int j0 = blockIdx.x * 128;
    const int s0 = blockIdx.y * 128;
    if (s0 + j0 + 254 < SEQ - 1) return;

    extern __shared__ float sm[];
    float* As = sm;
    float* Bs = sm + 2*128*GP;

    const int tid = threadIdx.x;
    const int wid = tid >> 5;
    const int lane = tid & 31;
    const int gid = lane >> 2;
    const int tig = lane & 3;
    const int wm = wid >> 2;
    const int wn = wid & 3;

    const float* Ag = g_q + ((size_t)b * SEQ + s0) * D_MODEL + (size_t)h * D_HEAD;
    const float* Bg = Er + (size_t)j0 * D_HEAD;

    float c[4][4][4];
#pragma unroll
    for (int mt = 0; mt < 4; mt++)
#pragma unroll
        for (int nt = 0; nt < 4; nt++)
#pragma unroll
            for (int r = 0; r < 4; r++) c[mt][nt][r] = 0.f;

    const int lrow = tid >> 3;
    const int lc4  = (tid & 7) * 4;

    float4 pa[4], pb[4];
#pragma unroll
    for (int i = 0; i < 4; i++) {
        pa[i] = *(const float4*)(Ag + (size_t)(lrow + i*32) * D_MODEL + lc4);
        pb[i] = *(const float4*)(Bg + (size_t)(lrow + i*32) * D_HEAD + lc4);
    }
#pragma unroll
    for (int i = 0; i < 4; i++) {
        float* da = As + (lrow + i*32) * GP + lc4;
        da[0]=f2tf_f(pa[i].x); da[1]=f2tf_f(pa[i].y); da[2]=f2tf_f(pa[i].z); da[3]=f2tf_f(pa[i].w);
        float* db = Bs + (lrow + i*32) * GP + lc4;
        db[0]=f2tf_f(pb[i].x); db[1]=f2tf_f(pb[i].y); db[2]=f2tf_f(pb[i].z); db[3]=f2tf_f(pb[i].w);
    }
    __syncthreads();

    for (int k0 = 0; k0 < D_HEAD; k0 += 32) {
        const int buf = (k0 >> 5) & 1;
        const bool has_next = (k0 + 32) < D_HEAD;
        if (has_next) {
#pragma unroll
            for (int i = 0; i < 4; i++) {
                pa[i] = *(const float4*)(Ag + (size_t)(lrow + i*32) * D_MODEL + k0 + 32 + lc4);
                pb[i] = *(const float4*)(Bg + (size_t)(lrow + i*32) * D_HEAD + k0 + 32 + lc4);
            }
        }
        const float* Ab = As + buf * 128 * GP;
        const float* Bb = Bs + buf * 128 * GP;
#pragma unroll
        for (int ks = 0; ks < 4; ks++) {
            const int kk = ks * 8;
            uint32_t a[4][4];
#pragma unroll
            for (int mt = 0; mt < 4; mt++) {
                const float* p = Ab + (wm*64 + mt*16 + gid) * GP + kk + tig;
                a[mt][0] = __float_as_uint(p[0]);
                a[mt][2] = __float_as_uint(p[4]);
                a[mt][1] = __float_as_uint(p[8*GP]);
                a[mt][3] = __float_as_uint(p[8*GP + 4]);
            }
#pragma unroll
            for (int nt = 0; nt < 4; nt++) {
                const float* q = Bb + (wn*32 + nt*8 + gid) * GP + kk + tig;
                uint32_t b0 = __float_as_uint(q[0]);
                uint32_t b1 = __float_as_uint(q[4]);
#pragma unroll
                for (int mt = 0; mt < 4; mt++)
                    mma_tf32(c[mt][nt][0], c[mt][nt][1], c[mt][nt][2], c[mt][nt][3],
                             a[mt][0], a[mt][1], a[mt][2], a[mt][3], b0, b1);
            }
        }
        if (has_next) {
            const int nb = buf ^ 1;
#pragma unroll
            for (int i = 0; i < 4; i++) {
                float* da = As + nb*128*GP + (lrow + i*32) * GP + lc4;
                da[0]=f2tf_f(pa[i].x); da[1]=f2tf_f(pa[i].y); da[2]=f2tf_f(pa[i].z); da[3]=f2tf_f(pa[i].w);
                float* db = Bs + nb*128*GP + (lrow + i*32) * GP + lc4;
                db[0]=f2tf_f(pb[i].x); db[1]=f2tf_f(pb[i].y); db[2]=f2tf_f(pb[i].z); db[3]=f2tf_f(pb[i].w);
            }
            __syncthreads();
        }
    }

    __half* dst = g_qer + (size_t)bh * SEQ * SEQ;
#pragma unroll
    for (int nt = 0; nt < 4; nt++) {
        const int col = j0 + wn*32 + nt*8 + 2*tig;   // even
#pragma unroll
        for (int mt = 0; mt < 4; mt++) {
            const int row = s0 + wm*64 + mt*16 + gid;
            *(__half2*)(dst + (size_t)row * SEQ + col) =
                __floats2half2_rn(c[mt][nt][0], c[mt][nt][1]);
            *(__half2*)(dst + (size_t)(row + 8) * SEQ + col) =
                __floats2half2_rn(c[mt][nt][2], c[mt][nt][3]);
        }
    }
}

// ============================================================
// Kernel 3: fp16 flash attention + rel bias.
// 8 warps x 16 rows; BK=64; m16n8k16 fp16 mma; Q frags in regs;
// cp.async double-buffered K/V; seeds prefetched into dead s_ regs.
// ============================================================
#define AHP 72     // halves per smem row (144 B, 16B-aligned, conflict-free)
#define ATT_SMEM_HALVES (2*64*AHP + 2*64*AHP + 128*AHP)
#define ATT_SMEM_BYTES (ATT_SMEM_HALVES * 2)   // 55296 B

__global__ __launch_bounds__(256, 2)
void attn_tc_kernel(float* __restrict__ out)
{
    const int qt = gridDim.x - 1 - blockIdx.x;   // big tiles first
    const int bh = blockIdx.y;
    const int b = bh >> 4, h = bh & 15;
    const int s0 = qt * 128;

    extern __shared__ __half smh[];
    __half* ks = smh;                    // [2][64][AHP]
    __half* vT = ks + 2*64*AHP;          // [2][64][AHP]
    __half* ps = vT + 2*64*AHP;          // [128][AHP]

    const int tid = threadIdx.x;
    const int wid = tid >> 5;
    const int lane = tid & 31;
    const int gid = lane >> 2;
    const int tig = lane & 3;
    const int r0 = wid*16 + gid;
    const int r1 = r0 + 8;
    const int sg0 = s0 + r0;
    const int sg1 = s0 + r1;

    const float*  qb  = g_q + ((size_t)b * SEQ + s0) * D_MODEL + (size_t)h * D_HEAD;
    const __half* kb  = g_k + (size_t)b * SEQ * D_MODEL + (size_t)h * D_HEAD;
    const __half* vtb = g_vT + (size_t)bh * D_HEAD * SEQ;
    const __half* qr0 = g_qer + (size_t)bh * SEQ * SEQ + (size_t)sg0 * SEQ;
    const __half* qr1 = g_qer + (size_t)bh * SEQ * SEQ + (size_t)sg1 * SEQ;

    // Q fragments resident in registers (fp16 packed)
    uint32_t qf[4][4];
#pragma unroll
    for (int k4 = 0; k4 < 4; k4++) {
        const int cc = k4*16 + 2*tig;
        const float2 x0 = *(const float2*)(qb + (size_t)r0 * D_MODEL + cc);
        const float2 x1 = *(const float2*)(qb + (size_t)r1 * D_MODEL + cc);
        const float2 x2 = *(const float2*)(qb + (size_t)r0 * D_MODEL + cc + 8);
        const float2 x3 = *(const float2*)(qb + (size_t)r1 * D_MODEL + cc + 8);
        qf[k4][0] = pack_h2(x0.x, x0.y);
        qf[k4][1] = pack_h2(x1.x, x1.y);
        qf[k4][2] = pack_h2(x2.x, x2.y);
        qf[k4][3] = pack_h2(x3.x, x3.y);
    }

    // cp.async chunk geometry: 512 K-chunks + 512 V-chunks of 16B, 4 per thread
    const uint32_t ks_base = (uint32_t)__cvta_generic_to_shared(ks);
    const uint32_t vt_base = (uint32_t)__cvta_generic_to_shared(vT);
    const int ci0 = tid * 2;
    const int ci1 = tid * 2 + 1;
    const int krow0 = ci0 >> 3, ko0 = (ci0 & 7) * 8;   // halves offset
    const int krow1 = ci1 >> 3, ko1 = (ci1 & 7) * 8;

    float o[8][4];
#pragma unroll
    for (int nt = 0; nt < 8; nt++) { o[nt][0]=0.f; o[nt][1]=0.f; o[nt][2]=0.f; o[nt][3]=0.f; }
    float m0v = -1e30f, m1v = -1e30f, l0v = 0.f, l1v = 0.f;
    const int nkt = 2 * qt + 2;

    // prologue: async-load tile 0 into buffer 0
    {
        cp_async16(ks_base + (krow0*AHP + ko0)*2, kb + (size_t)krow0 * D_MODEL + ko0);
        cp_async16(ks_base + (krow1*AHP + ko1)*2, kb + (size_t)krow1 * D_MODEL + ko1);
        cp_async16(vt_base + (krow0*AHP + ko0)*2, vtb + (size_t)krow0 * SEQ + ko0);
        cp_async16(vt_base + (krow1*AHP + ko1)*2, vtb + (size_t)krow1 * SEQ + ko1);
        CP_COMMIT();
    }

    // seed tile 0 rel bias into s_
    float s_[8][4];
    {
        const int ja0 = 2047 + 2*tig - sg0;
        const int jb0 = 2047 + 2*tig - sg1;
#pragma unroll
        for (int nt = 0; nt < 8; nt++) {
            int ja = ja0 + nt*8, jb = ja + 1;
            int jc = jb0 + nt*8, jd = jc + 1;
            ja = ja > 2047 ? 2047 : ja;  jb = jb > 2047 ? 2047 : jb;
            jc = jc > 2047 ? 2047 : jc;  jd = jd > 2047 ? 2047 : jd;
            s_[nt][0] = __half2float(qr0[ja]);
            s_[nt][1] = __half2float(qr0[jb]);
            s_[nt][2] = __half2float(qr1[jc]);
            s_[nt][3] = __half2float(qr1[jd]);
        }
    }

    for (int kt = 0; kt < nkt; kt++) {
        const int t0 = kt * 64;
        const int buf = kt & 1;

        CP_WAIT0();
        __syncthreads();   // tile kt data published; all warps done with buf^1

        // async-load tile kt+1 into the other buffer
        if (kt + 1 < nkt) {
            const int t0n = t0 + 64;
            const int boff = (buf ^ 1) * 64 * AHP * 2;
            cp_async16(ks_base + boff + (krow0*AHP + ko0)*2, kb + (size_t)(t0n + krow0) * D_MODEL + ko0);
            cp_async16(ks_base + boff + (krow1*AHP + ko1)*2, kb + (size_t)(t0n + krow1) * D_MODEL + ko1);
            cp_async16(vt_base + boff + (krow0*AHP + ko0)*2, vtb + (size_t)krow0 * SEQ + t0n + ko0);
            cp_async16(vt_base + boff + (krow1*AHP + ko1)*2, vtb + (size_t)krow1 * SEQ + t0n + ko1);
        }
        CP_COMMIT();

        const __half* ksb = ks + buf * 64 * AHP;
        const __half* vtf = vT + buf * 64 * AHP;

        // S += Q K^T  (fp16 mma, Q frags in regs)
#pragma unroll
        for (int k4 = 0; k4 < 4; k4++) {
            const int kk = k4 * 16;
#pragma unroll
            for (int nt = 0; nt < 8; nt++) {
                const __half* bp = ksb + (nt*8 + gid) * AHP + kk + 2*tig;
                uint32_t b0 = *(const uint32_t*)bp;
                uint32_t b1 = *(const uint32_t*)(bp + 8);
                mma_f16(s_[nt][0], s_[nt][1], s_[nt][2], s_[nt][3],
                        qf[k4][0], qf[k4][1], qf[k4][2], qf[k4][3], b0, b1);
            }
        }

        // ---- online softmax, row half 0 ----
        {
            float rmax = -1e30f;
#pragma unroll
            for (int nt = 0; nt < 8; nt++) {
                int tc = t0 + nt*8 + 2*tig;
                float v0 = s_[nt][0] * 0.125f;
                float v1 = s_[nt][1] * 0.125f;
                v0 = (tc     <= sg0) ? v0 : -1e30f;
                v1 = (tc + 1 <= sg0) ? v1 : -1e30f;
                s_[nt][0] = v0; s_[nt][1] = v1;
                rmax = fmaxf(rmax, fmaxf(v0, v1));
            }
            rmax = fmaxf(rmax, __shfl_xor_sync(0xffffffffu, rmax, 1));
            rmax = fmaxf(rmax, __shfl_xor_sync(0xffffffffu, rmax, 2));
            float mn = fmaxf(m0v, rmax);
            float alpha = __expf(m0v - mn);
            m0v = mn;
            float lsum = 0.f;
#pragma unroll
            for (int nt = 0; nt < 8; nt++) {
                float p0 = __expf(s_[nt][0] - mn);
                float p1 = __expf(s_[nt][1] - mn);
                lsum += p0 + p1;
                *(uint32_t*)(ps + r0*AHP + nt*8 + 2*tig) = pack_h2(p0, p1);
                o[nt][0] *= alpha; o[nt][1] *= alpha;
            }
            lsum += __shfl_xor_sync(0xffffffffu, lsum, 1);
            lsum += __shfl_xor_sync(0xffffffffu, lsum, 2);
            l0v = l0v * alpha + lsum;
        }
        // ---- row half 1 ----
        {
            float rmax = -1e30f;
#pragma unroll
            for (int nt = 0; nt < 8; nt++) {
                int tc = t0 + nt*8 + 2*tig;
                float v0 = s_[nt][2] * 0.125f;
                float v1 = s_[nt][3] * 0.125f;
                v0 = (tc     <= sg1) ? v0 : -1e30f;
                v1 = (tc + 1 <= sg1) ? v1 : -1e30f;
                s_[nt][2] = v0; s_[nt][3] = v1;
                rmax = fmaxf(rmax, fmaxf(v0, v1));
            }
            rmax = fmaxf(rmax, __shfl_xor_sync(0xffffffffu, rmax, 1));
            rmax = fmaxf(rmax, __shfl_xor_sync(0xffffffffu, rmax, 2));
            float mn = fmaxf(m1v, rmax);
            float alpha = __expf(m1v - mn);
            m1v = mn;
            float lsum = 0.f;
#pragma unroll
            for (int nt = 0; nt < 8; nt++) {
                float p0 = __expf(s_[nt][2] - mn);
                float p1 = __expf(s_[nt][3] - mn);
                lsum += p0 + p1;
                *(uint32_t*)(ps + r1*AHP + nt*8 + 2*tig) = pack_h2(p0, p1);
                o[nt][2] *= alpha; o[nt][3] *= alpha;
            }
            lsum += __shfl_xor_sync(0xffffffffu, lsum, 1);
            lsum += __shfl_xor_sync(0xffffffffu, lsum, 2);
            l1v = l1v * alpha + lsum;
        }

        // prefetch next tile's rel-bias seeds into the now-dead s_ regs
        {
            const int t0n = t0 + 64;
            const int ja0 = 2047 + t0n + 2*tig - sg0;
            const int jb0 = 2047 + t0n + 2*tig - sg1;
#pragma unroll
            for (int nt = 0; nt < 8; nt++) {
                int ja = ja0 + nt*8, jb = ja + 1;
                int jc = jb0 + nt*8, jd = jc + 1;
                ja = ja > 2047 ? 2047 : ja;  jb = jb > 2047 ? 2047 : jb;
                jc = jc > 2047 ? 2047 : jc;  jd = jd > 2047 ? 2047 : jd;
                s_[nt][0] = __half2float(qr0[ja]);
                s_[nt][1] = __half2float(qr0[jb]);
                s_[nt][2] = __half2float(qr1[jc]);
                s_[nt][3] = __half2float(qr1[jd]);
            }
        }

        __syncwarp();   // this warp's ps rows visible to its own lanes

        // O += P V  (fp16 mma)
#pragma unroll
        for (int k4 = 0; k4 < 4; k4++) {
            const int kk = k4 * 16;
            const __half* ap = ps + r0*AHP + kk + 2*tig;
            uint32_t a0 = *(const uint32_t*)ap;
            uint32_t a1 = *(const uint32_t*)(ap + 8*AHP);
            uint32_t a2 = *(const uint32_t*)(ap + 8);
            uint32_t a3 = *(const uint32_t*)(ap + 8*AHP + 8);
#pragma unroll
            for (int nt = 0; nt < 8; nt++) {
                const __half* bp = vtf + (nt*8 + gid) * AHP + kk + 2*tig;
                uint32_t b0 = *(const uint32_t*)bp;
                uint32_t b1 = *(const uint32_t*)(bp + 8);
                mma_f16(o[nt][0], o[nt][1], o[nt][2], o[nt][3],
                        a0, a1, a2, a3, b0, b1);
            }
        }
    }

    // epilogue: normalize and store (fp32)
    const float inv0 = 1.f / l0v;
    const float inv1 = 1.f / l1v;
    float* ob = out + (size_t)b * SEQ * D_MODEL + (size_t)h * D_HEAD;
#pragma unroll
    for (int nt = 0; nt < 8; nt++) {
        const int d = nt*8 + 2*tig;
        *(float2*)(ob + (size_t)sg0 * D_MODEL + d) = make_float2(o[nt][0]*inv0, o[nt][1]*inv0);
        *(float2*)(ob + (size_t)sg1 * D_MODEL + d) = make_float2(o[nt][2]*inv1, o[nt][3]*inv1);
    }
}

// ============================================================
// launcher
// ============================================================
extern "C" void kernel_launch(void* const* d_in, const int* in_sizes, int n_in,
                              void* d_out, int out_size)
{
    const float* x  = (const float*)d_in[0];
    const float* Wq = (const float*)d_in[1];
    const float* bq = (const float*)d_in[2];
    const float* Wk = (const float*)d_in[3];
    const float* bk = (const float*)d_in[4];
    const float* Wv = (const float*)d_in[5];
    const float* bv = (const float*)d_in[6];
    const float* Er = (const float*)d_in[7];
    float* out = (float*)d_out;

    cudaFuncSetAttribute(qkv_tc_kernel, cudaFuncAttributeMaxDynamicSharedMemorySize,
                         GEMM_SMEM_BYTES);
    cudaFuncSetAttribute(qer_tc_kernel, cudaFuncAttributeMaxDynamicSharedMemorySize,
                         GEMM_SMEM_BYTES);
    cudaFuncSetAttribute(attn_tc_kernel, cudaFuncAttributeMaxDynamicSharedMemorySize,
                         ATT_SMEM_BYTES);

    dim3 g1(D_MODEL / 128, (BATCH * SEQ) / 128, 3);
    qkv_tc_kernel<<<g1, 256, GEMM_SMEM_BYTES>>>(x, Wq, bq, Wk, bk, Wv, bv);

    dim3 g2(SEQ / 128, SEQ / 128, BHN);
    qer_tc_kernel<<<g2, 256, GEMM_SMEM_BYTES>>>(Er);

    dim3 g3(SEQ / 128, BHN);
    attn_tc_kernel<<<g3, 256, ATT_SMEM_BYTES>>>(out);
}

// round 7
// speedup vs baseline: 3.7751x; 1.1787x over previous
#include <cuda_runtime.h>
#include <cuda_fp16.h>
#include <math.h>
#include <stdint.h>

#define D_MODEL 1024
#define NUM_HEADS 16
#define D_HEAD 64
#define BATCH 2
#define SEQ 2048
#define BHN (BATCH*NUM_HEADS)

// -------- scratch (static device memory; no runtime allocation) --------
__device__ float  g_q  [(size_t)BATCH*SEQ*D_MODEL];          // 16 MB fp32
__device__ __half g_k  [(size_t)BATCH*SEQ*D_MODEL];          // 8 MB fp16
__device__ __half g_vT [(size_t)BHN*D_HEAD*SEQ];             // 8 MB fp16, [bh][d][s]
__device__ __half g_qer[(size_t)BHN*SEQ*SEQ];                // 256 MB fp16

// ---------------- mma helpers ----------------
__device__ __forceinline__ void mma_f16(float& c0, float& c1, float& c2, float& c3,
                                        uint32_t a0, uint32_t a1, uint32_t a2, uint32_t a3,
                                        uint32_t b0, uint32_t b1) {
    asm volatile(
        "mma.sync.aligned.m16n8k16.row.col.f32.f16.f16.f32 "
        "{%0,%1,%2,%3}, {%4,%5,%6,%7}, {%8,%9}, {%0,%1,%2,%3};"
        : "+f"(c0), "+f"(c1), "+f"(c2), "+f"(c3)
        : "r"(a0), "r"(a1), "r"(a2), "r"(a3), "r"(b0), "r"(b1));
}
__device__ __forceinline__ uint32_t pack_h2(float x, float y) {
    __half2 h = __floats2half2_rn(x, y);
    return *(uint32_t*)&h;
}
__device__ __forceinline__ void cp_async16(uint32_t saddr, const void* g) {
    asm volatile("cp.async.cg.shared.global [%0], [%1], 16;" :: "r"(saddr), "l"(g));
}
#define CP_COMMIT() asm volatile("cp.async.commit_group;")
#define CP_WAIT0()  asm volatile("cp.async.wait_group 0;")

// smem geometry for fp16 tensor-core GEMMs: [2 buf][128 rows][HP] halves
#define HP 40
#define GEMM_SMEM_BYTES (2*128*HP*2*2)   // two arrays (A,B) -> 40960 B

// ============================================================
// Kernel 1 (fp16 tensor core): Q/K/V projection.
// out[m,e] = sum_d x[m,d]*W[e,d] + b[e]; 128x128 tile, KC=32.
// z==0 -> g_q fp32; z==1 -> g_k fp16; z==2 -> g_vT fp16 transposed.
// ============================================================
__global__ __launch_bounds__(256, 2)
void qkv_tc_kernel(const float* __restrict__ x,
                   const float* __restrict__ Wq, const float* __restrict__ bq,
                   const float* __restrict__ Wk, const float* __restrict__ bk,
                   const float* __restrict__ Wv, const float* __restrict__ bv)
{
    const float* W; const float* bias;
    if (blockIdx.z == 0)      { W = Wq; bias = bq; }
    else if (blockIdx.z == 1) { W = Wk; bias = bk; }
    else                      { W = Wv; bias = bv; }

    extern __shared__ __half smh[];
    __half* As = smh;                // [2][128][HP]
    __half* Bs = smh + 2*128*HP;     // [2][128][HP]

    const int m0 = blockIdx.y * 128;
    const int n0 = blockIdx.x * 128;
    const int tid = threadIdx.x;
    const int wid = tid >> 5;
    const int lane = tid & 31;
    const int gid = lane >> 2;
    const int tig = lane & 3;
    const int wm = wid >> 2;
    const int wn = wid & 3;

    const float* Ag = x + (size_t)m0 * D_MODEL;
    const float* Bg = W + (size_t)n0 * D_MODEL;

    float c[4][4][4];
#pragma unroll
    for (int mt = 0; mt < 4; mt++)
#pragma unroll
        for (int nt = 0; nt < 4; nt++)
#pragma unroll
            for (int r = 0; r < 4; r++) c[mt][nt][r] = 0.f;

    const int lrow = tid >> 3;            // 0..31 (+i*32)
    const int lc4  = (tid & 7) * 4;       // 0,4,...,28 (halves)

    float4 pa[4], pb[4];
#pragma unroll
    for (int i = 0; i < 4; i++) {
        pa[i] = *(const float4*)(Ag + (size_t)(lrow + i*32) * D_MODEL + lc4);
        pb[i] = *(const float4*)(Bg + (size_t)(lrow + i*32) * D_MODEL + lc4);
    }
#pragma unroll
    for (int i = 0; i < 4; i++) {
        __half* da = As + (lrow + i*32) * HP + lc4;
        *(uint32_t*)da       = pack_h2(pa[i].x, pa[i].y);
        *(uint32_t*)(da + 2) = pack_h2(pa[i].z, pa[i].w);
        __half* db = Bs + (lrow + i*32) * HP + lc4;
        *(uint32_t*)db       = pack_h2(pb[i].x, pb[i].y);
        *(uint32_t*)(db + 2) = pack_h2(pb[i].z, pb[i].w);
    }
    __syncthreads();

    for (int k0 = 0; k0 < D_MODEL; k0 += 32) {
        const int buf = (k0 >> 5) & 1;
        const bool has_next = (k0 + 32) < D_MODEL;
        if (has_next) {
#pragma unroll
            for (int i = 0; i < 4; i++) {
                pa[i] = *(const float4*)(Ag + (size_t)(lrow + i*32) * D_MODEL + k0 + 32 + lc4);
                pb[i] = *(const float4*)(Bg + (size_t)(lrow + i*32) * D_MODEL + k0 + 32 + lc4);
            }
        }
        const __half* Ab = As + buf * 128 * HP;
        const __half* Bb = Bs + buf * 128 * HP;
#pragma unroll
        for (int ks = 0; ks < 2; ks++) {          // two k16 steps per 32-chunk
            const int kk = ks * 16;
            uint32_t a[4][4];
#pragma unroll
            for (int mt = 0; mt < 4; mt++) {
                const __half* p = Ab + (wm*64 + mt*16 + gid) * HP + kk + 2*tig;
                a[mt][0] = *(const uint32_t*)p;
                a[mt][1] = *(const uint32_t*)(p + 8*HP);
                a[mt][2] = *(const uint32_t*)(p + 8);
                a[mt][3] = *(const uint32_t*)(p + 8*HP + 8);
            }
#pragma unroll
            for (int nt = 0; nt < 4; nt++) {
                const __half* q = Bb + (wn*32 + nt*8 + gid) * HP + kk + 2*tig;
                uint32_t b0 = *(const uint32_t*)q;
                uint32_t b1 = *(const uint32_t*)(q + 8);
#pragma unroll
                for (int mt = 0; mt < 4; mt++)
                    mma_f16(c[mt][nt][0], c[mt][nt][1], c[mt][nt][2], c[mt][nt][3],
                            a[mt][0], a[mt][1], a[mt][2], a[mt][3], b0, b1);
            }
        }
        if (has_next) {
            const int nb = buf ^ 1;
#pragma unroll
            for (int i = 0; i < 4; i++) {
                __half* da = As + nb*128*HP + (lrow + i*32) * HP + lc4;
                *(uint32_t*)da       = pack_h2(pa[i].x, pa[i].y);
                *(uint32_t*)(da + 2) = pack_h2(pa[i].z, pa[i].w);
                __half* db = Bs + nb*128*HP + (lrow + i*32) * HP + lc4;
                *(uint32_t*)db       = pack_h2(pb[i].x, pb[i].y);
                *(uint32_t*)(db + 2) = pack_h2(pb[i].z, pb[i].w);
            }
            __syncthreads();
        }
    }

    if (blockIdx.z == 0) {
        // Q: fp32 row-major store with bias
#pragma unroll
        for (int nt = 0; nt < 4; nt++) {
            const int col = n0 + wn*32 + nt*8 + 2*tig;
            const float2 bb = *(const float2*)(bias + col);
#pragma unroll
            for (int mt = 0; mt < 4; mt++) {
                const int row = m0 + wm*64 + mt*16 + gid;
                *(float2*)(g_q + (size_t)row * D_MODEL + col) =
                    make_float2(c[mt][nt][0] + bb.x, c[mt][nt][1] + bb.y);
                *(float2*)(g_q + (size_t)(row + 8) * D_MODEL + col) =
                    make_float2(c[mt][nt][2] + bb.x, c[mt][nt][3] + bb.y);
            }
        }
    } else if (blockIdx.z == 1) {
        // K: fp16 row-major store
#pragma unroll
        for (int nt = 0; nt < 4; nt++) {
            const int col = n0 + wn*32 + nt*8 + 2*tig;   // even
            const float2 bb = *(const float2*)(bias + col);
#pragma unroll
            for (int mt = 0; mt < 4; mt++) {
                const int row = m0 + wm*64 + mt*16 + gid;
                *(__half2*)(g_k + (size_t)row * D_MODEL + col) =
                    __floats2half2_rn(c[mt][nt][0] + bb.x, c[mt][nt][1] + bb.y);
                *(__half2*)(g_k + (size_t)(row + 8) * D_MODEL + col) =
                    __floats2half2_rn(c[mt][nt][2] + bb.x, c[mt][nt][3] + bb.y);
            }
        }
    } else {
        // V: fp16 transposed store into g_vT[bh][d][s]
#pragma unroll
        for (int nt = 0; nt < 4; nt++) {
            const int col = n0 + wn*32 + nt*8 + 2*tig;
            const float2 bb = *(const float2*)(bias + col);
            const int hh = col >> 6;
            const int d0 = col & 63;
#pragma unroll
            for (int mt = 0; mt < 4; mt++) {
                const int row = m0 + wm*64 + mt*16 + gid;
                const int bidx = row >> 11;
                const int sidx = row & 2047;
                __half* base = g_vT + ((size_t)(bidx*NUM_HEADS + hh) * D_HEAD + d0) * SEQ;
                base[sidx]            = __float2half(c[mt][nt][0] + bb.x);
                base[SEQ + sidx]      = __float2half(c[mt][nt][1] + bb.y);
                base[sidx + 8]        = __float2half(c[mt][nt][2] + bb.x);
                base[SEQ + sidx + 8]  = __float2half(c[mt][nt][3] + bb.y);
            }
        }
    }
}

// ============================================================
// Kernel 2 (fp16 tensor core): QEr[bh][s][j] = q_head[s,:] . Er[j,:]
// fp16 output, band-skip.
// ============================================================
__global__ __launch_bounds__(256, 2)
void qer_tc_kernel(const float* __restrict__ Er)
{
    const int bh = blockIdx.z;
    const int b = bh >> 4, h = bh & 15;
    const int j0 = blockIdx.x * 128;
    const int s0 = blockIdx.y * 128;
    if (s0 + j0 + 254 < SEQ - 1) return;

    extern __shared__ __half smh[];
    __half* As = smh;
    __half* Bs = smh + 2*128*HP;

    const int tid = threadIdx.x;
    const int wid = tid >> 5;
    const int lane = tid & 31;
    const int gid = lane >> 2;
    const int tig = lane & 3;
    const int wm = wid >> 2;
    const int wn = wid & 3;

    const float* Ag = g_q + ((size_t)b * SEQ + s0) * D_MODEL + (size_t)h * D_HEAD;
    const float* Bg = Er + (size_t)j0 * D_HEAD;

    float c[4][4][4];
#pragma unroll
    for (int mt = 0; mt < 4; mt++)
#pragma unroll
        for (int nt = 0; nt < 4; nt++)
#pragma unroll
            for (int r = 0; r < 4; r++) c[mt][nt][r] = 0.f;

    const int lrow = tid >> 3;
    const int lc4  = (tid & 7) * 4;

    float4 pa[4], pb[4];
#pragma unroll
    for (int i = 0; i < 4; i++) {
        pa[i] = *(const float4*)(Ag + (size_t)(lrow + i*32) * D_MODEL + lc4);
        pb[i] = *(const float4*)(Bg + (size_t)(lrow + i*32) * D_HEAD + lc4);
    }
#pragma unroll
    for (int i = 0; i < 4; i++) {
        __half* da = As + (lrow + i*32) * HP + lc4;
        *(uint32_t*)da       = pack_h2(pa[i].x, pa[i].y);
        *(uint32_t*)(da + 2) = pack_h2(pa[i].z, pa[i].w);
        __half* db = Bs + (lrow + i*32) * HP + lc4;
        *(uint32_t*)db       = pack_h2(pb[i].x, pb[i].y);
        *(uint32_t*)(db + 2) = pack_h2(pb[i].z, pb[i].w);
    }
    __syncthreads();

    for (int k0 = 0; k0 < D_HEAD; k0 += 32) {
        const int buf = (k0 >> 5) & 1;
        const bool has_next = (k0 + 32) < D_HEAD;
        if (has_next) {
#pragma unroll
            for (int i = 0; i < 4; i++) {
                pa[i] = *(const float4*)(Ag + (size_t)(lrow + i*32) * D_MODEL + k0 + 32 + lc4);
                pb[i] = *(const float4*)(Bg + (size_t)(lrow + i*32) * D_HEAD + k0 + 32 + lc4);
            }
        }
        const __half* Ab = As + buf * 128 * HP;
        const __half* Bb = Bs + buf * 128 * HP;
#pragma unroll
        for (int ks = 0; ks < 2; ks++) {
            const int kk = ks * 16;
            uint32_t a[4][4];
#pragma unroll
            for (int mt = 0; mt < 4; mt++) {
                const __half* p = Ab + (wm*64 + mt*16 + gid) * HP + kk + 2*tig;
                a[mt][0] = *(const uint32_t*)p;
                a[mt][1] = *(const uint32_t*)(p + 8*HP);
                a[mt][2] = *(const uint32_t*)(p + 8);
                a[mt][3] = *(const uint32_t*)(p + 8*HP + 8);
            }
#pragma unroll
            for (int nt = 0; nt < 4; nt++) {
                const __half* q = Bb + (wn*32 + nt*8 + gid) * HP + kk + 2*tig;
                uint32_t b0 = *(const uint32_t*)q;
                uint32_t b1 = *(const uint32_t*)(q + 8);
#pragma unroll
                for (int mt = 0; mt < 4; mt++)
                    mma_f16(c[mt][nt][0], c[mt][nt][1], c[mt][nt][2], c[mt][nt][3],
                            a[mt][0], a[mt][1], a[mt][2], a[mt][3], b0, b1);
            }
        }
        if (has_next) {
            const int nb = buf ^ 1;
#pragma unroll
            for (int i = 0; i < 4; i++) {
                __half* da = As + nb*128*HP + (lrow + i*32) * HP + lc4;
                *(uint32_t*)da       = pack_h2(pa[i].x, pa[i].y);
                *(uint32_t*)(da + 2) = pack_h2(pa[i].z, pa[i].w);
                __half* db = Bs + nb*128*HP + (lrow + i*32) * HP + lc4;
                *(uint32_t*)db       = pack_h2(pb[i].x, pb[i].y);
                *(uint32_t*)(db + 2) = pack_h2(pb[i].z, pb[i].w);
            }
            __syncthreads();
        }
    }

    __half* dst = g_qer + (size_t)bh * SEQ * SEQ;
#pragma unroll
    for (int nt = 0; nt < 4; nt++) {
        const int col = j0 + wn*32 + nt*8 + 2*tig;   // even
#pragma unroll
        for (int mt = 0; mt < 4; mt++) {
            const int row = s0 + wm*64 + mt*16 + gid;
            *(__half2*)(dst + (size_t)row * SEQ + col) =
                __floats2half2_rn(c[mt][nt][0], c[mt][nt][1]);
            *(__half2*)(dst + (size_t)(row + 8) * SEQ + col) =
                __floats2half2_rn(c[mt][nt][2], c[mt][nt][3]);
        }
    }
}

// ============================================================
// Kernel 3: fp16 flash attention + rel bias.
// 8 warps x 16 rows; BK=64; m16n8k16 fp16 mma; Q frags in regs;
// cp.async double-buffered K/V; seeds prefetched into dead s_ regs.
// ============================================================
#define AHP 72     // halves per smem row (144 B, 16B-aligned, conflict-free)
#define ATT_SMEM_HALVES (2*64*AHP + 2*64*AHP + 128*AHP)
#define ATT_SMEM_BYTES (ATT_SMEM_HALVES * 2)   // 55296 B

__global__ __launch_bounds__(256, 2)
void attn_tc_kernel(float* __restrict__ out)
{
    const int qt = gridDim.x - 1 - blockIdx.x;   // big tiles first
    const int bh = blockIdx.y;
    const int b = bh >> 4, h = bh & 15;
    const int s0 = qt * 128;

    extern __shared__ __half smh[];
    __half* ks = smh;                    // [2][64][AHP]
    __half* vT = ks + 2*64*AHP;          // [2][64][AHP]
    __half* ps = vT + 2*64*AHP;          // [128][AHP]

    const int tid = threadIdx.x;
    const int wid = tid >> 5;
    const int lane = tid & 31;
    const int gid = lane >> 2;
    const int tig = lane & 3;
    const int r0 = wid*16 + gid;
    const int r1 = r0 + 8;
    const int sg0 = s0 + r0;
    const int sg1 = s0 + r1;

    const float*  qb  = g_q + ((size_t)b * SEQ + s0) * D_MODEL + (size_t)h * D_HEAD;
    const __half* kb  = g_k + (size_t)b * SEQ * D_MODEL + (size_t)h * D_HEAD;
    const __half* vtb = g_vT + (size_t)bh * D_HEAD * SEQ;
    const __half* qr0 = g_qer + (size_t)bh * SEQ * SEQ + (size_t)sg0 * SEQ;
    const __half* qr1 = g_qer + (size_t)bh * SEQ * SEQ + (size_t)sg1 * SEQ;

    // Q fragments resident in registers (fp16 packed)
    uint32_t qf[4][4];
#pragma unroll
    for (int k4 = 0; k4 < 4; k4++) {
        const int cc = k4*16 + 2*tig;
        const float2 x0 = *(const float2*)(qb + (size_t)r0 * D_MODEL + cc);
        const float2 x1 = *(const float2*)(qb + (size_t)r1 * D_MODEL + cc);
        const float2 x2 = *(const float2*)(qb + (size_t)r0 * D_MODEL + cc + 8);
        const float2 x3 = *(const float2*)(qb + (size_t)r1 * D_MODEL + cc + 8);
        qf[k4][0] = pack_h2(x0.x, x0.y);
        qf[k4][1] = pack_h2(x1.x, x1.y);
        qf[k4][2] = pack_h2(x2.x, x2.y);
        qf[k4][3] = pack_h2(x3.x, x3.y);
    }

    // cp.async chunk geometry: 512 K-chunks + 512 V-chunks of 16B, 4 per thread
    const uint32_t ks_base = (uint32_t)__cvta_generic_to_shared(ks);
    const uint32_t vt_base = (uint32_t)__cvta_generic_to_shared(vT);
    const int ci0 = tid * 2;
    const int ci1 = tid * 2 + 1;
    const int krow0 = ci0 >> 3, ko0 = (ci0 & 7) * 8;   // halves offset
    const int krow1 = ci1 >> 3, ko1 = (ci1 & 7) * 8;

    float o[8][4];
#pragma unroll
    for (int nt = 0; nt < 8; nt++) { o[nt][0]=0.f; o[nt][1]=0.f; o[nt][2]=0.f; o[nt][3]=0.f; }
    float m0v = -1e30f, m1v = -1e30f, l0v = 0.f, l1v = 0.f;
    const int nkt = 2 * qt + 2;

    // prologue: async-load tile 0 into buffer 0
    {
        cp_async16(ks_base + (krow0*AHP + ko0)*2, kb + (size_t)krow0 * D_MODEL + ko0);
        cp_async16(ks_base + (krow1*AHP + ko1)*2, kb + (size_t)krow1 * D_MODEL + ko1);
        cp_async16(vt_base + (krow0*AHP + ko0)*2, vtb + (size_t)krow0 * SEQ + ko0);
        cp_async16(vt_base + (krow1*AHP + ko1)*2, vtb + (size_t)krow1 * SEQ + ko1);
        CP_COMMIT();
    }

    // seed tile 0 rel bias into s_
    float s_[8][4];
    {
        const int ja0 = 2047 + 2*tig - sg0;
        const int jb0 = 2047 + 2*tig - sg1;
#pragma unroll
        for (int nt = 0; nt < 8; nt++) {
            int ja = ja0 + nt*8, jb = ja + 1;
            int jc = jb0 + nt*8, jd = jc + 1;
            ja = ja > 2047 ? 2047 : ja;  jb = jb > 2047 ? 2047 : jb;
            jc = jc > 2047 ? 2047 : jc;  jd = jd > 2047 ? 2047 : jd;
            s_[nt][0] = __half2float(qr0[ja]);
            s_[nt][1] = __half2float(qr0[jb]);
            s_[nt][2] = __half2float(qr1[jc]);
            s_[nt][3] = __half2float(qr1[jd]);
        }
    }

    for (int kt = 0; kt < nkt; kt++) {
        const int t0 = kt * 64;
        const int buf = kt & 1;

        CP_WAIT0();
        __syncthreads();   // tile kt data published; all warps done with buf^1

        // async-load tile kt+1 into the other buffer
        if (kt + 1 < nkt) {
            const int t0n = t0 + 64;
            const int boff = (buf ^ 1) * 64 * AHP * 2;
            cp_async16(ks_base + boff + (krow0*AHP + ko0)*2, kb + (size_t)(t0n + krow0) * D_MODEL + ko0);
            cp_async16(ks_base + boff + (krow1*AHP + ko1)*2, kb + (size_t)(t0n + krow1) * D_MODEL + ko1);
            cp_async16(vt_base + boff + (krow0*AHP + ko0)*2, vtb + (size_t)krow0 * SEQ + t0n + ko0);
            cp_async16(vt_base + boff + (krow1*AHP + ko1)*2, vtb + (size_t)krow1 * SEQ + t0n + ko1);
        }
        CP_COMMIT();

        const __half* ksb = ks + buf * 64 * AHP;
        const __half* vtf = vT + buf * 64 * AHP;

        // S += Q K^T  (fp16 mma, Q frags in regs)
#pragma unroll
        for (int k4 = 0; k4 < 4; k4++) {
            const int kk = k4 * 16;
#pragma unroll
            for (int nt = 0; nt < 8; nt++) {
                const __half* bp = ksb + (nt*8 + gid) * AHP + kk + 2*tig;
                uint32_t b0 = *(const uint32_t*)bp;
                uint32_t b1 = *(const uint32_t*)(bp + 8);
                mma_f16(s_[nt][0], s_[nt][1], s_[nt][2], s_[nt][3],
                        qf[k4][0], qf[k4][1], qf[k4][2], qf[k4][3], b0, b1);
            }
        }

        // ---- online softmax, row half 0 ----
        {
            float rmax = -1e30f;
#pragma unroll
            for (int nt = 0; nt < 8; nt++) {
                int tc = t0 + nt*8 + 2*tig;
                float v0 = s_[nt][0] * 0.125f;
                float v1 = s_[nt][1] * 0.125f;
                v0 = (tc     <= sg0) ? v0 : -1e30f;
                v1 = (tc + 1 <= sg0) ? v1 : -1e30f;
                s_[nt][0] = v0; s_[nt][1] = v1;
                rmax = fmaxf(rmax, fmaxf(v0, v1));
            }
            rmax = fmaxf(rmax, __shfl_xor_sync(0xffffffffu, rmax, 1));
            rmax = fmaxf(rmax, __shfl_xor_sync(0xffffffffu, rmax, 2));
            float mn = fmaxf(m0v, rmax);
            float alpha = __expf(m0v - mn);
            m0v = mn;
            float lsum = 0.f;
#pragma unroll
            for (int nt = 0; nt < 8; nt++) {
                float p0 = __expf(s_[nt][0] - mn);
                float p1 = __expf(s_[nt][1] - mn);
                lsum += p0 + p1;
                *(uint32_t*)(ps + r0*AHP + nt*8 + 2*tig) = pack_h2(p0, p1);
                o[nt][0] *= alpha; o[nt][1] *= alpha;
            }
            lsum += __shfl_xor_sync(0xffffffffu, lsum, 1);
            lsum += __shfl_xor_sync(0xffffffffu, lsum, 2);
            l0v = l0v * alpha + lsum;
        }
        // ---- row half 1 ----
        {
            float rmax = -1e30f;
#pragma unroll
            for (int nt = 0; nt < 8; nt++) {
                int tc = t0 + nt*8 + 2*tig;
                float v0 = s_[nt][2] * 0.125f;
                float v1 = s_[nt][3] * 0.125f;
                v0 = (tc     <= sg1) ? v0 : -1e30f;
                v1 = (tc + 1 <= sg1) ? v1 : -1e30f;
                s_[nt][2] = v0; s_[nt][3] = v1;
                rmax = fmaxf(rmax, fmaxf(v0, v1));
            }
            rmax = fmaxf(rmax, __shfl_xor_sync(0xffffffffu, rmax, 1));
            rmax = fmaxf(rmax, __shfl_xor_sync(0xffffffffu, rmax, 2));
            float mn = fmaxf(m1v, rmax);
            float alpha = __expf(m1v - mn);
            m1v = mn;
            float lsum = 0.f;
#pragma unroll
            for (int nt = 0; nt < 8; nt++) {
                float p0 = __expf(s_[nt][2] - mn);
                float p1 = __expf(s_[nt][3] - mn);
                lsum += p0 + p1;
                *(uint32_t*)(ps + r1*AHP + nt*8 + 2*tig) = pack_h2(p0, p1);
                o[nt][2] *= alpha; o[nt][3] *= alpha;
            }
            lsum += __shfl_xor_sync(0xffffffffu, lsum, 1);
            lsum += __shfl_xor_sync(0xffffffffu, lsum, 2);
            l1v = l1v * alpha + lsum;
        }

        // prefetch next tile's rel-bias seeds into the now-dead s_ regs
        {
            const int t0n = t0 + 64;
            const int ja0 = 2047 + t0n + 2*tig - sg0;
            const int jb0 = 2047 + t0n + 2*tig - sg1;
#pragma unroll
            for (int nt = 0; nt < 8; nt++) {
                int ja = ja0 + nt*8, jb = ja + 1;
                int jc = jb0 + nt*8, jd = jc + 1;
                ja = ja > 2047 ? 2047 : ja;  jb = jb > 2047 ? 2047 : jb;
                jc = jc > 2047 ? 2047 : jc;  jd = jd > 2047 ? 2047 : jd;
                s_[nt][0] = __half2float(qr0[ja]);
                s_[nt][1] = __half2float(qr0[jb]);
                s_[nt][2] = __half2float(qr1[jc]);
                s_[nt][3] = __half2float(qr1[jd]);
            }
        }

        __syncwarp();   // this warp's ps rows visible to its own lanes

        // O += P V  (fp16 mma)
#pragma unroll
        for (int k4 = 0; k4 < 4; k4++) {
            const int kk = k4 * 16;
            const __half* ap = ps + r0*AHP + kk + 2*tig;
            uint32_t a0 = *(const uint32_t*)ap;
            uint32_t a1 = *(const uint32_t*)(ap + 8*AHP);
            uint32_t a2 = *(const uint32_t*)(ap + 8);
            uint32_t a3 = *(const uint32_t*)(ap + 8*AHP + 8);
#pragma unroll
            for (int nt = 0; nt < 8; nt++) {
                const __half* bp = vtf + (nt*8 + gid) * AHP + kk + 2*tig;
                uint32_t b0 = *(const uint32_t*)bp;
                uint32_t b1 = *(const uint32_t*)(bp + 8);
                mma_f16(o[nt][0], o[nt][1], o[nt][2], o[nt][3],
                        a0, a1, a2, a3, b0, b1);
            }
        }
    }

    // epilogue: normalize and store (fp32)
    const float inv0 = 1.f / l0v;
    const float inv1 = 1.f / l1v;
    float* ob = out + (size_t)b * SEQ * D_MODEL + (size_t)h * D_HEAD;
#pragma unroll
    for (int nt = 0; nt < 8; nt++) {
        const int d = nt*8 + 2*tig;
        *(float2*)(ob + (size_t)sg0 * D_MODEL + d) = make_float2(o[nt][0]*inv0, o[nt][1]*inv0);
        *(float2*)(ob + (size_t)sg1 * D_MODEL + d) = make_float2(o[nt][2]*inv1, o[nt][3]*inv1);
    }
}

// ============================================================
// launcher
// ============================================================
extern "C" void kernel_launch(void* const* d_in, const int* in_sizes, int n_in,
                              void* d_out, int out_size)
{
    const float* x  = (const float*)d_in[0];
    const float* Wq = (const float*)d_in[1];
    const float* bq = (const float*)d_in[2];
    const float* Wk = (const float*)d_in[3];
    const float* bk = (const float*)d_in[4];
    const float* Wv = (const float*)d_in[5];
    const float* bv = (const float*)d_in[6];
    const float* Er = (const float*)d_in[7];
    float* out = (float*)d_out;

    cudaFuncSetAttribute(qkv_tc_kernel, cudaFuncAttributeMaxDynamicSharedMemorySize,
                         GEMM_SMEM_BYTES);
    cudaFuncSetAttribute(qer_tc_kernel, cudaFuncAttributeMaxDynamicSharedMemorySize,
                         GEMM_SMEM_BYTES);
    cudaFuncSetAttribute(attn_tc_kernel, cudaFuncAttributeMaxDynamicSharedMemorySize,
                         ATT_SMEM_BYTES);

    dim3 g1(D_MODEL / 128, (BATCH * SEQ) / 128, 3);
    qkv_tc_kernel<<<g1, 256, GEMM_SMEM_BYTES>>>(x, Wq, bq, Wk, bk, Wv, bv);

    dim3 g2(SEQ / 128, SEQ / 128, BHN);
    qer_tc_kernel<<<g2, 256, GEMM_SMEM_BYTES>>>(Er);

    dim3 g3(SEQ / 128, BHN);
    attn_tc_kernel<<<g3, 256, ATT_SMEM_BYTES>>>(out);
}